// round 1
// baseline (speedup 1.0000x reference)
#include <cuda_runtime.h>

#define HID 128
#define NH 4
#define NB 60000
#define NP 2000
#define NC 4000
#define EM_N 150000
#define EP_N 300000
#define EI_N 150000

// ---- scratch layout (floats) in one big device buffer ----
#define SZ_NBH (NB*HID)
#define OFF_XL     0
#define OFF_XR     (OFF_XL + NP*HID)
#define OFF_Q      (OFF_XR + SZ_NBH)
#define OFF_K      (OFF_Q + SZ_NBH)
#define OFF_V      (OFF_K + SZ_NBH)
#define OFF_GAT    (OFF_V + SZ_NBH)
#define OFF_TR     (OFF_GAT + SZ_NBH)
#define OFF_CTXSUM (OFF_TR + SZ_NBH)
#define OFF_MEAN   (OFF_CTXSUM + NC*HID)
#define OFF_SAGE   (OFF_MEAN + NC*HID)
#define OFF_CNT    (OFF_SAGE + NC*HID)
#define OFF_GLOGIT (OFF_CNT + NC)
#define OFF_TLOGIT (OFF_GLOGIT + EM_N*NH)
#define OFF_GMAX   (OFF_TLOGIT + EP_N*NH)
#define OFF_GSUM   (OFF_GMAX + NB*NH)
#define OFF_TMAX   (OFF_GSUM + NB*NH)
#define OFF_TSUM   (OFF_TMAX + NB*NH)
#define TOTAL_SCRATCH (OFF_TSUM + NB*NH)

__device__ __align__(256) float g_buf[TOTAL_SCRATCH];

// ---------------- helpers ----------------
__device__ __forceinline__ void atomicMaxF(float* addr, float val) {
    int* ia = (int*)addr;
    int old = *ia;
    while (__int_as_float(old) < val) {
        int assumed = old;
        old = atomicCAS(ia, assumed, __float_as_int(val));
        if (old == assumed) break;
    }
}

__device__ __forceinline__ void redAdd4(float* p, float a, float b, float c, float d) {
    asm volatile("red.global.add.v4.f32 [%0], {%1,%2,%3,%4};"
                 :: "l"(p), "f"(a), "f"(b), "f"(c), "f"(d) : "memory");
}

__device__ __forceinline__ float4 shfl4(float4 v, int src) {
    float4 r;
    r.x = __shfl_sync(0xffffffffu, v.x, src);
    r.y = __shfl_sync(0xffffffffu, v.y, src);
    r.z = __shfl_sync(0xffffffffu, v.z, src);
    r.w = __shfl_sync(0xffffffffu, v.w, src);
    return r;
}

// ---------------- init ----------------
__global__ void init_kernel(const float* __restrict__ gb) {
    int i = blockIdx.x * blockDim.x + threadIdx.x;
    if (i < NB*HID) g_buf[OFF_GAT + i] = gb[i & (HID-1)];
    if (i < NB*NH) {
        float ninf = __int_as_float(0xff800000);
        g_buf[OFF_GMAX + i] = ninf;
        g_buf[OFF_TMAX + i] = ninf;
        g_buf[OFF_GSUM + i] = 0.f;
        g_buf[OFF_TSUM + i] = 0.f;
    }
    if (i < NC*HID) g_buf[OFF_CTXSUM + i] = 0.f;
    if (i < NC) g_buf[OFF_CNT + i] = 0.f;
}

// ---------------- generic 128x128 row GEMM: out[r,:] = A[r,:] @ W (+bias)(+=) ----------------
// grid.x = ceil(nrows/64), grid.y = 2 (column half), block = 256
__global__ void gemm128(const float* __restrict__ A, const float* __restrict__ W,
                        const float* __restrict__ bias, float* __restrict__ out,
                        int nrows, int accum)
{
    __shared__ float2 Ws[HID*32];   // 128 rows x 64 cols (as float2) = 32 KB
    const int colHalf = blockIdx.y;
    const int tid = threadIdx.x;
    for (int idx = tid; idx < HID*32; idx += 256) {
        int i = idx >> 5, c2 = idx & 31;
        Ws[idx] = ((const float2*)(W + i*HID + colHalf*64))[c2];
    }
    __syncthreads();
    const int warp = tid >> 5, lane = tid & 31;
    float2 b2 = make_float2(0.f, 0.f);
    if (bias) b2 = ((const float2*)(bias + colHalf*64))[lane];

    int rbase = blockIdx.x * 64;
    for (int rp = warp*2; rp < 64; rp += 16) {
        int r0 = rbase + rp, r1 = r0 + 1;
        if (r0 >= nrows) continue;           // warp-uniform
        bool has1 = (r1 < nrows);
        float4 a0 = ((const float4*)(A + (size_t)r0*HID))[lane];
        float4 a1 = has1 ? ((const float4*)(A + (size_t)r1*HID))[lane]
                         : make_float4(0.f,0.f,0.f,0.f);
        float2 acc0 = make_float2(0.f,0.f), acc1 = make_float2(0.f,0.f);
        #pragma unroll
        for (int l2 = 0; l2 < 32; l2++) {
            float4 av0 = shfl4(a0, l2);
            float4 av1 = shfl4(a1, l2);
            float2 w;
            w = Ws[(l2*4+0)*32 + lane];
            acc0.x += av0.x*w.x; acc0.y += av0.x*w.y; acc1.x += av1.x*w.x; acc1.y += av1.x*w.y;
            w = Ws[(l2*4+1)*32 + lane];
            acc0.x += av0.y*w.x; acc0.y += av0.y*w.y; acc1.x += av1.y*w.x; acc1.y += av1.y*w.y;
            w = Ws[(l2*4+2)*32 + lane];
            acc0.x += av0.z*w.x; acc0.y += av0.z*w.y; acc1.x += av1.z*w.x; acc1.y += av1.z*w.y;
            w = Ws[(l2*4+3)*32 + lane];
            acc0.x += av0.w*w.x; acc0.y += av0.w*w.y; acc1.x += av1.w*w.x; acc1.y += av1.w*w.y;
        }
        {
            float2* po = ((float2*)(out + (size_t)r0*HID + colHalf*64)) + lane;
            float2 o = make_float2(acc0.x + b2.x, acc0.y + b2.y);
            if (accum) { float2 pv = *po; o.x += pv.x; o.y += pv.y; }
            *po = o;
        }
        if (has1) {
            float2* po = ((float2*)(out + (size_t)r1*HID + colHalf*64)) + lane;
            float2 o = make_float2(acc1.x + b2.x, acc1.y + b2.y);
            if (accum) { float2 pv = *po; o.x += pv.x; o.y += pv.y; }
            *po = o;
        }
    }
}

// ---------------- GATv2 edge passes ----------------
__global__ void gat_logit_kernel(const int* __restrict__ em, const float* __restrict__ att) {
    int w = (blockIdx.x << 3) + (threadIdx.x >> 5);
    if (w >= EM_N) return;
    int lane = threadIdx.x & 31;
    int s = em[w], d = em[EM_N + w];
    float4 xl = ((const float4*)(g_buf + OFF_XL + (size_t)s*HID))[lane];
    float4 xr = ((const float4*)(g_buf + OFF_XR + (size_t)d*HID))[lane];
    float4 at = ((const float4*)att)[lane];
    float ex = xl.x + xr.x; ex = ex > 0.f ? ex : 0.2f*ex;
    float ey = xl.y + xr.y; ey = ey > 0.f ? ey : 0.2f*ey;
    float ez = xl.z + xr.z; ez = ez > 0.f ? ez : 0.2f*ez;
    float ew = xl.w + xr.w; ew = ew > 0.f ? ew : 0.2f*ew;
    float p = ex*at.x + ey*at.y + ez*at.z + ew*at.w;
    p += __shfl_xor_sync(0xffffffffu, p, 1);
    p += __shfl_xor_sync(0xffffffffu, p, 2);
    p += __shfl_xor_sync(0xffffffffu, p, 4);
    if ((lane & 7) == 0) {
        int h = lane >> 3;
        g_buf[OFF_GLOGIT + (size_t)w*NH + h] = p;
        atomicMaxF(&g_buf[OFF_GMAX + (size_t)d*NH + h], p);
    }
}

__global__ void softmax_kernel(const int* __restrict__ dst, float* __restrict__ logits,
                               const float* __restrict__ mx, float* __restrict__ sm, int nE) {
    int i = blockIdx.x * blockDim.x + threadIdx.x;
    if (i >= nE*NH) return;
    int e = i >> 2, h = i & 3;
    int d = dst[e];
    float ex = __expf(logits[i] - mx[d*NH + h]);
    logits[i] = ex;
    atomicAdd(&sm[d*NH + h], ex);
}

__global__ void gat_scatter_kernel(const int* __restrict__ em) {
    int w = (blockIdx.x << 3) + (threadIdx.x >> 5);
    if (w >= EM_N) return;
    int lane = threadIdx.x & 31;
    int s = em[w], d = em[EM_N + w];
    int h = lane >> 3;
    float alpha = g_buf[OFF_GLOGIT + (size_t)w*NH + h] /
                  (g_buf[OFF_GSUM + (size_t)d*NH + h] + 1e-16f);
    float4 xl = ((const float4*)(g_buf + OFF_XL + (size_t)s*HID))[lane];
    redAdd4(g_buf + OFF_GAT + (size_t)d*HID + lane*4,
            xl.x*alpha, xl.y*alpha, xl.z*alpha, xl.w*alpha);
}

// ---------------- TransformerConv edge passes ----------------
__global__ void tr_logit_kernel(const int* __restrict__ ep, const float* __restrict__ ea,
                                const float* __restrict__ tWe) {
    int w = (blockIdx.x << 3) + (threadIdx.x >> 5);
    if (w >= EP_N) return;
    int lane = threadIdx.x & 31;
    int s = ep[w], d = ep[EP_N + w];
    float e = ea[w];
    float4 we = ((const float4*)tWe)[lane];
    float4 kv = ((const float4*)(g_buf + OFF_K + (size_t)s*HID))[lane];
    float4 qv = ((const float4*)(g_buf + OFF_Q + (size_t)d*HID))[lane];
    float p = qv.x*(kv.x + e*we.x) + qv.y*(kv.y + e*we.y)
            + qv.z*(kv.z + e*we.z) + qv.w*(kv.w + e*we.w);
    p += __shfl_xor_sync(0xffffffffu, p, 1);
    p += __shfl_xor_sync(0xffffffffu, p, 2);
    p += __shfl_xor_sync(0xffffffffu, p, 4);
    if ((lane & 7) == 0) {
        int h = lane >> 3;
        float lg = p * 0.17677669529663689f;   // 1/sqrt(32)
        g_buf[OFF_TLOGIT + (size_t)w*NH + h] = lg;
        atomicMaxF(&g_buf[OFF_TMAX + (size_t)d*NH + h], lg);
    }
}

__global__ void tr_scatter_kernel(const int* __restrict__ ep, const float* __restrict__ ea,
                                  const float* __restrict__ tWe) {
    int w = (blockIdx.x << 3) + (threadIdx.x >> 5);
    if (w >= EP_N) return;
    int lane = threadIdx.x & 31;
    int s = ep[w], d = ep[EP_N + w];
    float e = ea[w];
    int h = lane >> 3;
    float alpha = g_buf[OFF_TLOGIT + (size_t)w*NH + h] /
                  (g_buf[OFF_TSUM + (size_t)d*NH + h] + 1e-16f);
    float4 we = ((const float4*)tWe)[lane];
    float4 vv = ((const float4*)(g_buf + OFF_V + (size_t)s*HID))[lane];
    redAdd4(g_buf + OFF_TR + (size_t)d*HID + lane*4,
            (vv.x + e*we.x)*alpha, (vv.y + e*we.y)*alpha,
            (vv.z + e*we.z)*alpha, (vv.w + e*we.w)*alpha);
}

// ---------------- SAGE ----------------
__global__ void sage_scatter_kernel(const int* __restrict__ ei, const float* __restrict__ x_ball) {
    int w = (blockIdx.x << 3) + (threadIdx.x >> 5);
    if (w >= EI_N) return;
    int lane = threadIdx.x & 31;
    int s = ei[w], d = ei[EI_N + w];
    float4 xb = ((const float4*)(x_ball + (size_t)s*HID))[lane];
    redAdd4(g_buf + OFF_CTXSUM + (size_t)d*HID + lane*4, xb.x, xb.y, xb.z, xb.w);
    if (lane == 0) atomicAdd(&g_buf[OFF_CNT + d], 1.0f);
}

__global__ void mean_kernel() {
    int i = blockIdx.x * blockDim.x + threadIdx.x;
    if (i >= NC*HID) return;
    int c = i >> 7;
    g_buf[OFF_MEAN + i] = g_buf[OFF_CTXSUM + i] / fmaxf(g_buf[OFF_CNT + c], 1.0f);
}

// ---------------- LayerNorm (A + B [+ C]) ----------------
__global__ void ln_kernel(const float* __restrict__ A, const float* __restrict__ B,
                          const float* __restrict__ C, const float* __restrict__ g,
                          const float* __restrict__ b, float* __restrict__ out, int n) {
    int r = (blockIdx.x << 3) + (threadIdx.x >> 5);
    if (r >= n) return;
    int lane = threadIdx.x & 31;
    float4 p = ((const float4*)(A + (size_t)r*HID))[lane];
    float4 q = ((const float4*)(B + (size_t)r*HID))[lane];
    p.x += q.x; p.y += q.y; p.z += q.z; p.w += q.w;
    if (C) {
        float4 c4 = ((const float4*)(C + (size_t)r*HID))[lane];
        p.x += c4.x; p.y += c4.y; p.z += c4.z; p.w += c4.w;
    }
    float s = p.x + p.y + p.z + p.w;
    float sq = p.x*p.x + p.y*p.y + p.z*p.z + p.w*p.w;
    #pragma unroll
    for (int off = 16; off >= 1; off >>= 1) {
        s  += __shfl_xor_sync(0xffffffffu, s, off);
        sq += __shfl_xor_sync(0xffffffffu, sq, off);
    }
    float mu = s * (1.0f/HID);
    float var = sq * (1.0f/HID) - mu*mu;
    float rstd = rsqrtf(var + 1e-5f);
    float4 gg = ((const float4*)g)[lane];
    float4 bb = ((const float4*)b)[lane];
    float4 o;
    o.x = (p.x - mu)*rstd*gg.x + bb.x;
    o.y = (p.y - mu)*rstd*gg.y + bb.y;
    o.z = (p.z - mu)*rstd*gg.z + bb.z;
    o.w = (p.w - mu)*rstd*gg.w + bb.w;
    ((float4*)(out + (size_t)r*HID))[lane] = o;
}

__global__ void copy_player_kernel(const float* __restrict__ xp, float* __restrict__ out) {
    int i = blockIdx.x * blockDim.x + threadIdx.x;
    if (i < NP*HID/4) {
        ((float4*)out)[(size_t)(NB+NC)*HID/4 + i] = ((const float4*)xp)[i];
    }
}

// ---------------- launch ----------------
extern "C" void kernel_launch(void* const* d_in, const int* in_sizes, int n_in,
                              void* d_out, int out_size)
{
    const float* x_ball    = (const float*)d_in[0];
    const float* x_player  = (const float*)d_in[1];
    const float* x_context = (const float*)d_in[2];
    const int*   em   = (const int*)d_in[3];
    const int*   ep   = (const int*)d_in[4];
    const int*   ei   = (const int*)d_in[5];
    const float* ea_p = (const float*)d_in[6];
    const float* gWl  = (const float*)d_in[7];
    const float* gWr  = (const float*)d_in[8];
    const float* gatt = (const float*)d_in[9];
    const float* gb   = (const float*)d_in[10];
    const float* tWq  = (const float*)d_in[11];
    const float* tbq  = (const float*)d_in[12];
    const float* tWk  = (const float*)d_in[13];
    const float* tbk  = (const float*)d_in[14];
    const float* tWv  = (const float*)d_in[15];
    const float* tbv  = (const float*)d_in[16];
    const float* tWe  = (const float*)d_in[17];
    const float* tWs  = (const float*)d_in[18];
    const float* tbs  = (const float*)d_in[19];
    const float* sWl  = (const float*)d_in[20];
    const float* sbl  = (const float*)d_in[21];
    const float* sWr  = (const float*)d_in[22];
    const float* lbg  = (const float*)d_in[23];
    const float* lbb  = (const float*)d_in[24];
    const float* lcg  = (const float*)d_in[25];
    const float* lcb  = (const float*)d_in[26];
    float* out = (float*)d_out;

    float* base = nullptr;
    cudaGetSymbolAddress((void**)&base, g_buf);
    float* s_xl     = base + OFF_XL;
    float* s_xr     = base + OFF_XR;
    float* s_q      = base + OFF_Q;
    float* s_k      = base + OFF_K;
    float* s_v      = base + OFF_V;
    float* s_gat    = base + OFF_GAT;
    float* s_tr     = base + OFF_TR;
    float* s_mean   = base + OFF_MEAN;
    float* s_sage   = base + OFF_SAGE;
    float* s_glogit = base + OFF_GLOGIT;
    float* s_tlogit = base + OFF_TLOGIT;
    float* s_gmax   = base + OFF_GMAX;
    float* s_gsum   = base + OFF_GSUM;
    float* s_tmax   = base + OFF_TMAX;
    float* s_tsum   = base + OFF_TSUM;

    const int T = 256;

    // init accumulators / stat buffers
    init_kernel<<<(NB*HID + T-1)/T, T>>>(gb);

    // dense transforms
    dim3 gNB((NB + 63)/64, 2), gNP((NP + 63)/64, 2), gNC((NC + 63)/64, 2);
    gemm128<<<gNP, T>>>(x_player, gWl, nullptr, s_xl, NP, 0);
    gemm128<<<gNB, T>>>(x_ball,  gWr, nullptr, s_xr, NB, 0);
    gemm128<<<gNB, T>>>(x_ball,  tWq, tbq,     s_q,  NB, 0);
    gemm128<<<gNB, T>>>(x_ball,  tWk, tbk,     s_k,  NB, 0);
    gemm128<<<gNB, T>>>(x_ball,  tWv, tbv,     s_v,  NB, 0);
    gemm128<<<gNB, T>>>(x_ball,  tWs, tbs,     s_tr, NB, 0);   // skip pre-loaded into tr acc

    // GATv2: logits+max -> exp+sum -> weighted scatter
    gat_logit_kernel<<<(EM_N + 7)/8, T>>>(em, gatt);
    softmax_kernel<<<(EM_N*NH + T-1)/T, T>>>(em + EM_N, s_glogit, s_gmax, s_gsum, EM_N);
    gat_scatter_kernel<<<(EM_N + 7)/8, T>>>(em);

    // TransformerConv
    tr_logit_kernel<<<(EP_N + 7)/8, T>>>(ep, ea_p, tWe);
    softmax_kernel<<<(EP_N*NH + T-1)/T, T>>>(ep + EP_N, s_tlogit, s_tmax, s_tsum, EP_N);
    tr_scatter_kernel<<<(EP_N + 7)/8, T>>>(ep, ea_p, tWe);

    // SAGE mean
    sage_scatter_kernel<<<(EI_N + 7)/8, T>>>(ei, x_ball);
    mean_kernel<<<(NC*HID + T-1)/T, T>>>();
    gemm128<<<gNC, T>>>(x_context, sWr, nullptr, s_sage, NC, 0);
    gemm128<<<gNC, T>>>(s_mean,    sWl, sbl,     s_sage, NC, 1);

    // outputs
    ln_kernel<<<(NB + 7)/8, T>>>(s_gat, s_tr, x_ball, lbg, lbb, out, NB);
    ln_kernel<<<(NC + 7)/8, T>>>(s_sage, x_context, nullptr, lcg, lcb, out + (size_t)NB*HID, NC);
    copy_player_kernel<<<(NP*HID/4 + T-1)/T, T>>>(x_player, out);
}

// round 2
// speedup vs baseline: 1.3711x; 1.3711x over previous
#include <cuda_runtime.h>

#define HID 128
#define NH 4
#define NB 60000
#define NP 2000
#define NC 4000
#define EM_N 150000
#define EP_N 300000
#define EI_N 150000

// ---- scratch layout (floats) in one big device buffer ----
#define SZ_NBH (NB*HID)
#define OFF_XL     0
#define OFF_XR     (OFF_XL + NP*HID)
#define OFF_Q      (OFF_XR + SZ_NBH)
#define OFF_K      (OFF_Q + SZ_NBH)
#define OFF_V      (OFF_K + SZ_NBH)
#define OFF_GAT    (OFF_V + SZ_NBH)
#define OFF_TR     (OFF_GAT + SZ_NBH)
#define OFF_CTXSUM (OFF_TR + SZ_NBH)
#define OFF_MEAN   (OFF_CTXSUM + NC*HID)
#define OFF_SAGE   (OFF_MEAN + NC*HID)
#define OFF_CNT    (OFF_SAGE + NC*HID)
#define OFF_GLOGIT (OFF_CNT + NC)
#define OFF_TLOGIT (OFF_GLOGIT + EM_N*NH)
#define OFF_GMAX   (OFF_TLOGIT + EP_N*NH)
#define OFF_GSUM   (OFF_GMAX + NB*NH)
#define OFF_TMAX   (OFF_GSUM + NB*NH)
#define OFF_TSUM   (OFF_TMAX + NB*NH)
#define TOTAL_SCRATCH (OFF_TSUM + NB*NH)

__device__ __align__(256) float g_buf[TOTAL_SCRATCH];

// ---------------- helpers ----------------
__device__ __forceinline__ void atomicMaxF(float* addr, float val) {
    int* ia = (int*)addr;
    int old = *ia;
    while (__int_as_float(old) < val) {
        int assumed = old;
        old = atomicCAS(ia, assumed, __float_as_int(val));
        if (old == assumed) break;
    }
}

__device__ __forceinline__ void redAdd4(float* p, float a, float b, float c, float d) {
    asm volatile("red.global.add.v4.f32 [%0], {%1,%2,%3,%4};"
                 :: "l"(p), "f"(a), "f"(b), "f"(c), "f"(d) : "memory");
}

// ---------------- init ----------------
__global__ void init_kernel(const float* __restrict__ gb) {
    int i = blockIdx.x * blockDim.x + threadIdx.x;
    if (i < NB*HID) g_buf[OFF_GAT + i] = gb[i & (HID-1)];
    if (i < NB*NH) {
        float ninf = __int_as_float(0xff800000);
        g_buf[OFF_GMAX + i] = ninf;
        g_buf[OFF_TMAX + i] = ninf;
        g_buf[OFF_GSUM + i] = 0.f;
        g_buf[OFF_TSUM + i] = 0.f;
    }
    if (i < NC*HID) g_buf[OFF_CTXSUM + i] = 0.f;
    if (i < NC) g_buf[OFF_CNT + i] = 0.f;
}

// ---------------- register-blocked SMEM GEMM ----------------
// out[r, colHalf*64 + c] = A[r,:] @ W[:, colHalf*64 + c] (+bias)(+= prev)
// grid = (ceil(nrows/128), 2), block = 128 threads (16 row-groups x 8 col-groups)
// smem: As[128][132] (padded), Ws[128][64]. Micro-tile 8x8 per thread.
// Inner 4-k step: 16 LDS.128 vs 256 FFMA -> FFMA-bound.
#define AS_STRIDE 132
#define GEMM_SMEM ((128*AS_STRIDE + 128*64) * 4)

__global__ void __launch_bounds__(128)
gemm128_v2(const float* __restrict__ A, const float* __restrict__ W,
           const float* __restrict__ bias, float* __restrict__ out,
           int nrows, int accum)
{
    extern __shared__ float sm[];
    float* As = sm;                 // [128][132]
    float* Ws = sm + 128*AS_STRIDE; // [128][64]
    const int colHalf = blockIdx.y;
    const int tid = threadIdx.x;
    const int rbase = blockIdx.x * 128;

    // load W column-half: 128 x 64 floats = 2048 float4
    for (int idx = tid; idx < 128*16; idx += 128) {
        int k = idx >> 4, c4 = idx & 15;
        ((float4*)(Ws + k*64))[c4] =
            ((const float4*)(W + (size_t)k*HID + colHalf*64))[c4];
    }
    // load A tile: 128 x 128 floats = 4096 float4 (zero-pad OOB rows)
    for (int idx = tid; idx < 128*32; idx += 128) {
        int r = idx >> 5, c4 = idx & 31;
        int gr = rbase + r;
        float4 v = make_float4(0.f, 0.f, 0.f, 0.f);
        if (gr < nrows) v = ((const float4*)(A + (size_t)gr*HID))[c4];
        *(float4*)(As + r*AS_STRIDE + c4*4) = v;
    }
    __syncthreads();

    const int tc = tid & 7;   // col group: cols tc*8 .. tc*8+7 (within half)
    const int tr = tid >> 3;  // row group: rows tr*8 .. tr*8+7

    float acc[8][8];
    #pragma unroll
    for (int i = 0; i < 8; i++)
        #pragma unroll
        for (int j = 0; j < 8; j++) acc[i][j] = 0.f;

    #pragma unroll 4
    for (int k4 = 0; k4 < 32; k4++) {
        float4 a4[8];
        #pragma unroll
        for (int i = 0; i < 8; i++)
            a4[i] = *(const float4*)(As + (tr*8 + i)*AS_STRIDE + k4*4);
        #pragma unroll
        for (int kk = 0; kk < 4; kk++) {
            const float* wrow = Ws + (k4*4 + kk)*64 + tc*8;
            float4 w0 = *(const float4*)(wrow);
            float4 w1 = *(const float4*)(wrow + 4);
            #pragma unroll
            for (int i = 0; i < 8; i++) {
                float av = (kk == 0) ? a4[i].x : (kk == 1) ? a4[i].y
                         : (kk == 2) ? a4[i].z : a4[i].w;
                acc[i][0] += av * w0.x; acc[i][1] += av * w0.y;
                acc[i][2] += av * w0.z; acc[i][3] += av * w0.w;
                acc[i][4] += av * w1.x; acc[i][5] += av * w1.y;
                acc[i][6] += av * w1.z; acc[i][7] += av * w1.w;
            }
        }
    }

    float4 bv0 = make_float4(0.f,0.f,0.f,0.f), bv1 = bv0;
    if (bias) {
        bv0 = *(const float4*)(bias + colHalf*64 + tc*8);
        bv1 = *(const float4*)(bias + colHalf*64 + tc*8 + 4);
    }
    #pragma unroll
    for (int i = 0; i < 8; i++) {
        int gr = rbase + tr*8 + i;
        if (gr >= nrows) break;
        float* po = out + (size_t)gr*HID + colHalf*64 + tc*8;
        float4 o0 = make_float4(acc[i][0]+bv0.x, acc[i][1]+bv0.y,
                                acc[i][2]+bv0.z, acc[i][3]+bv0.w);
        float4 o1 = make_float4(acc[i][4]+bv1.x, acc[i][5]+bv1.y,
                                acc[i][6]+bv1.z, acc[i][7]+bv1.w);
        if (accum) {
            float4 p0 = *(const float4*)(po);
            float4 p1 = *(const float4*)(po + 4);
            o0.x += p0.x; o0.y += p0.y; o0.z += p0.z; o0.w += p0.w;
            o1.x += p1.x; o1.y += p1.y; o1.z += p1.z; o1.w += p1.w;
        }
        *(float4*)(po)     = o0;
        *(float4*)(po + 4) = o1;
    }
}

// ---------------- GATv2 edge passes ----------------
__global__ void gat_logit_kernel(const int* __restrict__ em, const float* __restrict__ att) {
    int w = (blockIdx.x << 3) + (threadIdx.x >> 5);
    if (w >= EM_N) return;
    int lane = threadIdx.x & 31;
    int s = em[w], d = em[EM_N + w];
    float4 xl = ((const float4*)(g_buf + OFF_XL + (size_t)s*HID))[lane];
    float4 xr = ((const float4*)(g_buf + OFF_XR + (size_t)d*HID))[lane];
    float4 at = ((const float4*)att)[lane];
    float ex = xl.x + xr.x; ex = ex > 0.f ? ex : 0.2f*ex;
    float ey = xl.y + xr.y; ey = ey > 0.f ? ey : 0.2f*ey;
    float ez = xl.z + xr.z; ez = ez > 0.f ? ez : 0.2f*ez;
    float ew = xl.w + xr.w; ew = ew > 0.f ? ew : 0.2f*ew;
    float p = ex*at.x + ey*at.y + ez*at.z + ew*at.w;
    p += __shfl_xor_sync(0xffffffffu, p, 1);
    p += __shfl_xor_sync(0xffffffffu, p, 2);
    p += __shfl_xor_sync(0xffffffffu, p, 4);
    if ((lane & 7) == 0) {
        int h = lane >> 3;
        g_buf[OFF_GLOGIT + (size_t)w*NH + h] = p;
        atomicMaxF(&g_buf[OFF_GMAX + (size_t)d*NH + h], p);
    }
}

__global__ void softmax_kernel(const int* __restrict__ dst, float* __restrict__ logits,
                               const float* __restrict__ mx, float* __restrict__ sm, int nE) {
    int i = blockIdx.x * blockDim.x + threadIdx.x;
    if (i >= nE*NH) return;
    int e = i >> 2, h = i & 3;
    int d = dst[e];
    float ex = __expf(logits[i] - mx[d*NH + h]);
    logits[i] = ex;
    atomicAdd(&sm[d*NH + h], ex);
}

__global__ void gat_scatter_kernel(const int* __restrict__ em) {
    int w = (blockIdx.x << 3) + (threadIdx.x >> 5);
    if (w >= EM_N) return;
    int lane = threadIdx.x & 31;
    int s = em[w], d = em[EM_N + w];
    int h = lane >> 3;
    float alpha = g_buf[OFF_GLOGIT + (size_t)w*NH + h] /
                  (g_buf[OFF_GSUM + (size_t)d*NH + h] + 1e-16f);
    float4 xl = ((const float4*)(g_buf + OFF_XL + (size_t)s*HID))[lane];
    redAdd4(g_buf + OFF_GAT + (size_t)d*HID + lane*4,
            xl.x*alpha, xl.y*alpha, xl.z*alpha, xl.w*alpha);
}

// ---------------- TransformerConv edge passes ----------------
__global__ void tr_logit_kernel(const int* __restrict__ ep, const float* __restrict__ ea,
                                const float* __restrict__ tWe) {
    int w = (blockIdx.x << 3) + (threadIdx.x >> 5);
    if (w >= EP_N) return;
    int lane = threadIdx.x & 31;
    int s = ep[w], d = ep[EP_N + w];
    float e = ea[w];
    float4 we = ((const float4*)tWe)[lane];
    float4 kv = ((const float4*)(g_buf + OFF_K + (size_t)s*HID))[lane];
    float4 qv = ((const float4*)(g_buf + OFF_Q + (size_t)d*HID))[lane];
    float p = qv.x*(kv.x + e*we.x) + qv.y*(kv.y + e*we.y)
            + qv.z*(kv.z + e*we.z) + qv.w*(kv.w + e*we.w);
    p += __shfl_xor_sync(0xffffffffu, p, 1);
    p += __shfl_xor_sync(0xffffffffu, p, 2);
    p += __shfl_xor_sync(0xffffffffu, p, 4);
    if ((lane & 7) == 0) {
        int h = lane >> 3;
        float lg = p * 0.17677669529663689f;   // 1/sqrt(32)
        g_buf[OFF_TLOGIT + (size_t)w*NH + h] = lg;
        atomicMaxF(&g_buf[OFF_TMAX + (size_t)d*NH + h], lg);
    }
}

__global__ void tr_scatter_kernel(const int* __restrict__ ep, const float* __restrict__ ea,
                                  const float* __restrict__ tWe) {
    int w = (blockIdx.x << 3) + (threadIdx.x >> 5);
    if (w >= EP_N) return;
    int lane = threadIdx.x & 31;
    int s = ep[w], d = ep[EP_N + w];
    float e = ea[w];
    int h = lane >> 3;
    float alpha = g_buf[OFF_TLOGIT + (size_t)w*NH + h] /
                  (g_buf[OFF_TSUM + (size_t)d*NH + h] + 1e-16f);
    float4 we = ((const float4*)tWe)[lane];
    float4 vv = ((const float4*)(g_buf + OFF_V + (size_t)s*HID))[lane];
    redAdd4(g_buf + OFF_TR + (size_t)d*HID + lane*4,
            (vv.x + e*we.x)*alpha, (vv.y + e*we.y)*alpha,
            (vv.z + e*we.z)*alpha, (vv.w + e*we.w)*alpha);
}

// ---------------- SAGE ----------------
__global__ void sage_scatter_kernel(const int* __restrict__ ei, const float* __restrict__ x_ball) {
    int w = (blockIdx.x << 3) + (threadIdx.x >> 5);
    if (w >= EI_N) return;
    int lane = threadIdx.x & 31;
    int s = ei[w], d = ei[EI_N + w];
    float4 xb = ((const float4*)(x_ball + (size_t)s*HID))[lane];
    redAdd4(g_buf + OFF_CTXSUM + (size_t)d*HID + lane*4, xb.x, xb.y, xb.z, xb.w);
    if (lane == 0) atomicAdd(&g_buf[OFF_CNT + d], 1.0f);
}

__global__ void mean_kernel() {
    int i = blockIdx.x * blockDim.x + threadIdx.x;
    if (i >= NC*HID) return;
    int c = i >> 7;
    g_buf[OFF_MEAN + i] = g_buf[OFF_CTXSUM + i] / fmaxf(g_buf[OFF_CNT + c], 1.0f);
}

// ---------------- LayerNorm (A + B [+ C]) ----------------
__global__ void ln_kernel(const float* __restrict__ A, const float* __restrict__ B,
                          const float* __restrict__ C, const float* __restrict__ g,
                          const float* __restrict__ b, float* __restrict__ out, int n) {
    int r = (blockIdx.x << 3) + (threadIdx.x >> 5);
    if (r >= n) return;
    int lane = threadIdx.x & 31;
    float4 p = ((const float4*)(A + (size_t)r*HID))[lane];
    float4 q = ((const float4*)(B + (size_t)r*HID))[lane];
    p.x += q.x; p.y += q.y; p.z += q.z; p.w += q.w;
    if (C) {
        float4 c4 = ((const float4*)(C + (size_t)r*HID))[lane];
        p.x += c4.x; p.y += c4.y; p.z += c4.z; p.w += c4.w;
    }
    float s = p.x + p.y + p.z + p.w;
    float sq = p.x*p.x + p.y*p.y + p.z*p.z + p.w*p.w;
    #pragma unroll
    for (int off = 16; off >= 1; off >>= 1) {
        s  += __shfl_xor_sync(0xffffffffu, s, off);
        sq += __shfl_xor_sync(0xffffffffu, sq, off);
    }
    float mu = s * (1.0f/HID);
    float var = sq * (1.0f/HID) - mu*mu;
    float rstd = rsqrtf(var + 1e-5f);
    float4 gg = ((const float4*)g)[lane];
    float4 bb = ((const float4*)b)[lane];
    float4 o;
    o.x = (p.x - mu)*rstd*gg.x + bb.x;
    o.y = (p.y - mu)*rstd*gg.y + bb.y;
    o.z = (p.z - mu)*rstd*gg.z + bb.z;
    o.w = (p.w - mu)*rstd*gg.w + bb.w;
    ((float4*)(out + (size_t)r*HID))[lane] = o;
}

__global__ void copy_player_kernel(const float* __restrict__ xp, float* __restrict__ out) {
    int i = blockIdx.x * blockDim.x + threadIdx.x;
    if (i < NP*HID/4) {
        ((float4*)out)[(size_t)(NB+NC)*HID/4 + i] = ((const float4*)xp)[i];
    }
}

// ---------------- launch ----------------
extern "C" void kernel_launch(void* const* d_in, const int* in_sizes, int n_in,
                              void* d_out, int out_size)
{
    const float* x_ball    = (const float*)d_in[0];
    const float* x_player  = (const float*)d_in[1];
    const float* x_context = (const float*)d_in[2];
    const int*   em   = (const int*)d_in[3];
    const int*   ep   = (const int*)d_in[4];
    const int*   ei   = (const int*)d_in[5];
    const float* ea_p = (const float*)d_in[6];
    const float* gWl  = (const float*)d_in[7];
    const float* gWr  = (const float*)d_in[8];
    const float* gatt = (const float*)d_in[9];
    const float* gb   = (const float*)d_in[10];
    const float* tWq  = (const float*)d_in[11];
    const float* tbq  = (const float*)d_in[12];
    const float* tWk  = (const float*)d_in[13];
    const float* tbk  = (const float*)d_in[14];
    const float* tWv  = (const float*)d_in[15];
    const float* tbv  = (const float*)d_in[16];
    const float* tWe  = (const float*)d_in[17];
    const float* tWs  = (const float*)d_in[18];
    const float* tbs  = (const float*)d_in[19];
    const float* sWl  = (const float*)d_in[20];
    const float* sbl  = (const float*)d_in[21];
    const float* sWr  = (const float*)d_in[22];
    const float* lbg  = (const float*)d_in[23];
    const float* lbb  = (const float*)d_in[24];
    const float* lcg  = (const float*)d_in[25];
    const float* lcb  = (const float*)d_in[26];
    float* out = (float*)d_out;

    float* base = nullptr;
    cudaGetSymbolAddress((void**)&base, g_buf);
    float* s_xl     = base + OFF_XL;
    float* s_xr     = base + OFF_XR;
    float* s_q      = base + OFF_Q;
    float* s_k      = base + OFF_K;
    float* s_v      = base + OFF_V;
    float* s_gat    = base + OFF_GAT;
    float* s_tr     = base + OFF_TR;
    float* s_mean   = base + OFF_MEAN;
    float* s_sage   = base + OFF_SAGE;
    float* s_glogit = base + OFF_GLOGIT;
    float* s_tlogit = base + OFF_TLOGIT;
    float* s_gmax   = base + OFF_GMAX;
    float* s_gsum   = base + OFF_GSUM;
    float* s_tmax   = base + OFF_TMAX;
    float* s_tsum   = base + OFF_TSUM;

    const int T = 256;

    static int smem_set = 0;
    cudaFuncSetAttribute(gemm128_v2, cudaFuncAttributeMaxDynamicSharedMemorySize, GEMM_SMEM);
    (void)smem_set;

    // init accumulators / stat buffers
    init_kernel<<<(NB*HID + T-1)/T, T>>>(gb);

    // dense transforms
    dim3 gNB((NB + 127)/128, 2), gNP((NP + 127)/128, 2), gNC((NC + 127)/128, 2);
    gemm128_v2<<<gNP, 128, GEMM_SMEM>>>(x_player, gWl, nullptr, s_xl, NP, 0);
    gemm128_v2<<<gNB, 128, GEMM_SMEM>>>(x_ball,  gWr, nullptr, s_xr, NB, 0);
    gemm128_v2<<<gNB, 128, GEMM_SMEM>>>(x_ball,  tWq, tbq,     s_q,  NB, 0);
    gemm128_v2<<<gNB, 128, GEMM_SMEM>>>(x_ball,  tWk, tbk,     s_k,  NB, 0);
    gemm128_v2<<<gNB, 128, GEMM_SMEM>>>(x_ball,  tWv, tbv,     s_v,  NB, 0);
    gemm128_v2<<<gNB, 128, GEMM_SMEM>>>(x_ball,  tWs, tbs,     s_tr, NB, 0);   // skip pre-loaded into tr acc

    // GATv2: logits+max -> exp+sum -> weighted scatter
    gat_logit_kernel<<<(EM_N + 7)/8, T>>>(em, gatt);
    softmax_kernel<<<(EM_N*NH + T-1)/T, T>>>(em + EM_N, s_glogit, s_gmax, s_gsum, EM_N);
    gat_scatter_kernel<<<(EM_N + 7)/8, T>>>(em);

    // TransformerConv
    tr_logit_kernel<<<(EP_N + 7)/8, T>>>(ep, ea_p, tWe);
    softmax_kernel<<<(EP_N*NH + T-1)/T, T>>>(ep + EP_N, s_tlogit, s_tmax, s_tsum, EP_N);
    tr_scatter_kernel<<<(EP_N + 7)/8, T>>>(ep, ea_p, tWe);

    // SAGE mean
    sage_scatter_kernel<<<(EI_N + 7)/8, T>>>(ei, x_ball);
    mean_kernel<<<(NC*HID + T-1)/T, T>>>();
    gemm128_v2<<<gNC, 128, GEMM_SMEM>>>(x_context, sWr, nullptr, s_sage, NC, 0);
    gemm128_v2<<<gNC, 128, GEMM_SMEM>>>(s_mean,    sWl, sbl,     s_sage, NC, 1);

    // outputs
    ln_kernel<<<(NB + 7)/8, T>>>(s_gat, s_tr, x_ball, lbg, lbb, out, NB);
    ln_kernel<<<(NC + 7)/8, T>>>(s_sage, x_context, nullptr, lcg, lcb, out + (size_t)NB*HID, NC);
    copy_player_kernel<<<(NP*HID/4 + T-1)/T, T>>>(x_player, out);
}

// round 4
// speedup vs baseline: 2.3268x; 1.6970x over previous
#include <cuda_runtime.h>
#include <cuda_bf16.h>
#include <cstdint>

#define HID 128
#define NH 4
#define NB 60000
#define NP 2000
#define NC 4000
#define EM_N 150000
#define EP_N 300000
#define EI_N 150000
#define NTILE 469          // ceil(NB/128)

// ---- scratch layout (floats) in one big device buffer ----
#define SZ_NBH (NB*HID)
#define OFF_XL     0
#define OFF_XR     (OFF_XL + NP*HID)
#define OFF_Q      (OFF_XR + SZ_NBH)
#define OFF_K      (OFF_Q + SZ_NBH)
#define OFF_V      (OFF_K + SZ_NBH)
#define OFF_GAT    (OFF_V + SZ_NBH)
#define OFF_TR     (OFF_GAT + SZ_NBH)
#define OFF_CTXSUM (OFF_TR + SZ_NBH)
#define OFF_MEAN   (OFF_CTXSUM + NC*HID)
#define OFF_SAGE   (OFF_MEAN + NC*HID)
#define OFF_CNT    (OFF_SAGE + NC*HID)
#define OFF_GLOGIT (OFF_CNT + NC)
#define OFF_TLOGIT (OFF_GLOGIT + EM_N*NH)
#define OFF_GMAX   (OFF_TLOGIT + EP_N*NH)
#define OFF_GSUM   (OFF_GMAX + NB*NH)
#define OFF_TMAX   (OFF_GSUM + NB*NH)
#define OFF_TSUM   (OFF_TMAX + NB*NH)
#define TOTAL_SCRATCH (OFF_TSUM + NB*NH)

__device__ __align__(256) float g_buf[TOTAL_SCRATCH];

// ---------------- MMA helpers (sm_80-class, valid on plain sm_103) ----------------
__device__ __forceinline__ uint32_t smem_u32(const void* p) {
    uint32_t a;
    asm("{ .reg .u64 t; cvta.to.shared.u64 t, %1; cvt.u32.u64 %0, t; }" : "=r"(a) : "l"(p));
    return a;
}
__device__ __forceinline__ void ldsm4(uint32_t& r0, uint32_t& r1, uint32_t& r2, uint32_t& r3,
                                      uint32_t addr) {
    asm volatile("ldmatrix.sync.aligned.m8n8.x4.shared.b16 {%0,%1,%2,%3}, [%4];"
                 : "=r"(r0), "=r"(r1), "=r"(r2), "=r"(r3) : "r"(addr));
}
__device__ __forceinline__ void ldsm4t(uint32_t& r0, uint32_t& r1, uint32_t& r2, uint32_t& r3,
                                       uint32_t addr) {
    asm volatile("ldmatrix.sync.aligned.m8n8.x4.trans.shared.b16 {%0,%1,%2,%3}, [%4];"
                 : "=r"(r0), "=r"(r1), "=r"(r2), "=r"(r3) : "r"(addr));
}
__device__ __forceinline__ void mma16816(float* C, const uint32_t* A, uint32_t B0, uint32_t B1) {
    asm volatile("mma.sync.aligned.m16n8k16.row.col.f32.bf16.bf16.f32 "
                 "{%0,%1,%2,%3}, {%4,%5,%6,%7}, {%8,%9}, {%0,%1,%2,%3};"
                 : "+f"(C[0]), "+f"(C[1]), "+f"(C[2]), "+f"(C[3])
                 : "r"(A[0]), "r"(A[1]), "r"(A[2]), "r"(A[3]), "r"(B0), "r"(B1));
}

// ---------------- fused 5-output HMMA GEMM over x_ball ----------------
// smem: bf16 tiles with row stride 136 (conflict-free ldmatrix: 68 b32 -> 4r mod 32)
#define STR 136
#define SMA_H 0
#define SMA_L 34816
#define SMW_H 69632
#define SMW_L 104448
#define SMEM_BIG5 139264

__global__ void __launch_bounds__(256)
big5_mma(const float* __restrict__ xball,
         const float* __restrict__ w0, const float* __restrict__ w1,
         const float* __restrict__ w2, const float* __restrict__ w3,
         const float* __restrict__ w4,
         float* __restrict__ o0, float* __restrict__ o1, float* __restrict__ o2,
         float* __restrict__ o3, float* __restrict__ o4,
         const float* __restrict__ b0, const float* __restrict__ b1,
         const float* __restrict__ b2, const float* __restrict__ b3)
{
    extern __shared__ char smem[];
    const uint32_t sb = smem_u32(smem);
    const int tid = threadIdx.x, lane = tid & 31, warp = tid >> 5;
    const int wm = warp >> 1, wn = warp & 1;     // 4x2 warp grid: 32-row x 64-col tiles
    const int rbase = blockIdx.x * 128;

    // ---- stage A tile as hi/lo bf16 (in-kernel convert, zero-pad OOB rows) ----
    for (int idx = tid; idx < 8192; idx += 256) {
        int row = idx >> 6, kp = idx & 63;
        int grow = rbase + row;
        float2 v = make_float2(0.f, 0.f);
        if (grow < NB) v = ((const float2*)(xball + (size_t)grow * HID))[kp];
        __nv_bfloat162 h2 = __float22bfloat162_rn(v);
        float2 lo = make_float2(v.x - __bfloat162float(h2.x),
                                v.y - __bfloat162float(h2.y));
        __nv_bfloat162 l2 = __float22bfloat162_rn(lo);
        uint32_t off = (uint32_t)(row * STR + kp * 2) * 2;
        *(uint32_t*)(smem + SMA_H + off) = *(uint32_t*)&h2;
        *(uint32_t*)(smem + SMA_L + off) = *(uint32_t*)&l2;
    }

    const float* Wg5[5]    = {w0, w1, w2, w3, w4};
    float*       outs[5]   = {o0, o1, o2, o3, o4};
    const float* biases[5] = {b0, b1, b2, b3, nullptr};

    const int gid = lane >> 2, tig = lane & 3;
    const int sub = lane >> 3, lr = lane & 7;
    const int f_r = ((sub & 1) << 3) + lr;   // row offset within 16x16 frag block
    const int f_c = (sub >> 1) << 3;         // col offset (b16 units)

    for (int i = 0; i < 5; i++) {
        // ---- stage W_i (k-major, straight copy) as hi/lo bf16 ----
        const float* Wg = Wg5[i];
        for (int idx = tid; idx < 8192; idx += 256) {
            int k = idx >> 6, np = idx & 63;
            float2 v = ((const float2*)(Wg + (size_t)k * HID))[np];
            __nv_bfloat162 h2 = __float22bfloat162_rn(v);
            float2 lo = make_float2(v.x - __bfloat162float(h2.x),
                                    v.y - __bfloat162float(h2.y));
            __nv_bfloat162 l2 = __float22bfloat162_rn(lo);
            uint32_t off = (uint32_t)(k * STR + np * 2) * 2;
            *(uint32_t*)(smem + SMW_H + off) = *(uint32_t*)&h2;
            *(uint32_t*)(smem + SMW_L + off) = *(uint32_t*)&l2;
        }
        __syncthreads();   // also covers A staging on first iteration

        float acc[2][8][4];
        #pragma unroll
        for (int mt = 0; mt < 2; mt++)
            #pragma unroll
            for (int j = 0; j < 8; j++)
                #pragma unroll
                for (int c = 0; c < 4; c++) acc[mt][j][c] = 0.f;

        #pragma unroll
        for (int ks = 0; ks < 8; ks++) {
            const int K0 = ks * 16;
            uint32_t ah[2][4], al[2][4];
            #pragma unroll
            for (int mt = 0; mt < 2; mt++) {
                uint32_t ad = sb + SMA_H +
                    (uint32_t)((wm*32 + mt*16 + f_r) * STR + K0 + f_c) * 2;
                ldsm4(ah[mt][0], ah[mt][1], ah[mt][2], ah[mt][3], ad);
                ldsm4(al[mt][0], al[mt][1], al[mt][2], al[mt][3], ad + (SMA_L - SMA_H));
            }
            uint32_t bh[4][4], bl[4][4];
            #pragma unroll
            for (int nt = 0; nt < 4; nt++) {
                uint32_t wd = sb + SMW_H +
                    (uint32_t)((K0 + f_r) * STR + wn*64 + nt*16 + f_c) * 2;
                ldsm4t(bh[nt][0], bh[nt][1], bh[nt][2], bh[nt][3], wd);
                ldsm4t(bl[nt][0], bl[nt][1], bl[nt][2], bl[nt][3], wd + (SMW_L - SMW_H));
            }
            #pragma unroll
            for (int mt = 0; mt < 2; mt++)
                #pragma unroll
                for (int nt = 0; nt < 4; nt++)
                    #pragma unroll
                    for (int h = 0; h < 2; h++) {
                        float* C = acc[mt][nt*2 + h];
                        mma16816(C, ah[mt], bh[nt][2*h], bh[nt][2*h+1]);
                        mma16816(C, ah[mt], bl[nt][2*h], bl[nt][2*h+1]);
                        mma16816(C, al[mt], bh[nt][2*h], bh[nt][2*h+1]);
                    }
        }

        // ---- epilogue: acc -> gmem (+bias) ----
        const float* bias = biases[i];
        float* outp = outs[i];
        #pragma unroll
        for (int mt = 0; mt < 2; mt++) {
            int r0g = rbase + wm*32 + mt*16 + gid;
            #pragma unroll
            for (int j = 0; j < 8; j++) {
                int cn = wn*64 + j*8 + tig*2;
                float bx = bias ? bias[cn]   : 0.f;
                float by = bias ? bias[cn+1] : 0.f;
                if (r0g < NB)
                    *(float2*)(outp + (size_t)r0g*HID + cn) =
                        make_float2(acc[mt][j][0] + bx, acc[mt][j][1] + by);
                if (r0g + 8 < NB)
                    *(float2*)(outp + (size_t)(r0g+8)*HID + cn) =
                        make_float2(acc[mt][j][2] + bx, acc[mt][j][3] + by);
            }
        }
        __syncthreads();   // all warps done with W smem before restage
    }
}

// ---------------- helpers ----------------
__device__ __forceinline__ void atomicMaxF(float* addr, float val) {
    int* ia = (int*)addr;
    int old = *ia;
    while (__int_as_float(old) < val) {
        int assumed = old;
        old = atomicCAS(ia, assumed, __float_as_int(val));
        if (old == assumed) break;
    }
}
__device__ __forceinline__ void redAdd4(float* p, float a, float b, float c, float d) {
    asm volatile("red.global.add.v4.f32 [%0], {%1,%2,%3,%4};"
                 :: "l"(p), "f"(a), "f"(b), "f"(c), "f"(d) : "memory");
}

// ---------------- init ----------------
__global__ void init_kernel(const float* __restrict__ gb) {
    int i = blockIdx.x * blockDim.x + threadIdx.x;
    if (i < NB*HID) g_buf[OFF_GAT + i] = gb[i & (HID-1)];
    if (i < NB*NH) {
        float ninf = __int_as_float(0xff800000);
        g_buf[OFF_GMAX + i] = ninf;
        g_buf[OFF_TMAX + i] = ninf;
        g_buf[OFF_GSUM + i] = 0.f;
        g_buf[OFF_TSUM + i] = 0.f;
    }
    if (i < NC*HID) g_buf[OFF_CTXSUM + i] = 0.f;
    if (i < NC) g_buf[OFF_CNT + i] = 0.f;
}

// ---------------- SIMT GEMM (small matrices only) ----------------
#define AS_STRIDE 132
#define GEMM_SMEM ((128*AS_STRIDE + 128*64) * 4)

__global__ void __launch_bounds__(128)
gemm128_v2(const float* __restrict__ A, const float* __restrict__ W,
           const float* __restrict__ bias, float* __restrict__ out,
           int nrows, int accum)
{
    extern __shared__ float sm[];
    float* As = sm;
    float* Ws = sm + 128*AS_STRIDE;
    const int colHalf = blockIdx.y;
    const int tid = threadIdx.x;
    const int rbase = blockIdx.x * 128;

    for (int idx = tid; idx < 128*16; idx += 128) {
        int k = idx >> 4, c4 = idx & 15;
        ((float4*)(Ws + k*64))[c4] =
            ((const float4*)(W + (size_t)k*HID + colHalf*64))[c4];
    }
    for (int idx = tid; idx < 128*32; idx += 128) {
        int r = idx >> 5, c4 = idx & 31;
        int gr = rbase + r;
        float4 v = make_float4(0.f, 0.f, 0.f, 0.f);
        if (gr < nrows) v = ((const float4*)(A + (size_t)gr*HID))[c4];
        *(float4*)(As + r*AS_STRIDE + c4*4) = v;
    }
    __syncthreads();

    const int tc = tid & 7, tr = tid >> 3;
    float acc[8][8];
    #pragma unroll
    for (int i = 0; i < 8; i++)
        #pragma unroll
        for (int j = 0; j < 8; j++) acc[i][j] = 0.f;

    #pragma unroll 4
    for (int k4 = 0; k4 < 32; k4++) {
        float4 a4[8];
        #pragma unroll
        for (int i = 0; i < 8; i++)
            a4[i] = *(const float4*)(As + (tr*8 + i)*AS_STRIDE + k4*4);
        #pragma unroll
        for (int kk = 0; kk < 4; kk++) {
            const float* wrow = Ws + (k4*4 + kk)*64 + tc*8;
            float4 w0 = *(const float4*)(wrow);
            float4 w1 = *(const float4*)(wrow + 4);
            #pragma unroll
            for (int i = 0; i < 8; i++) {
                float av = (kk == 0) ? a4[i].x : (kk == 1) ? a4[i].y
                         : (kk == 2) ? a4[i].z : a4[i].w;
                acc[i][0] += av * w0.x; acc[i][1] += av * w0.y;
                acc[i][2] += av * w0.z; acc[i][3] += av * w0.w;
                acc[i][4] += av * w1.x; acc[i][5] += av * w1.y;
                acc[i][6] += av * w1.z; acc[i][7] += av * w1.w;
            }
        }
    }

    float4 bv0 = make_float4(0.f,0.f,0.f,0.f), bv1 = bv0;
    if (bias) {
        bv0 = *(const float4*)(bias + colHalf*64 + tc*8);
        bv1 = *(const float4*)(bias + colHalf*64 + tc*8 + 4);
    }
    #pragma unroll
    for (int i = 0; i < 8; i++) {
        int gr = rbase + tr*8 + i;
        if (gr >= nrows) break;
        float* po = out + (size_t)gr*HID + colHalf*64 + tc*8;
        float4 o0 = make_float4(acc[i][0]+bv0.x, acc[i][1]+bv0.y,
                                acc[i][2]+bv0.z, acc[i][3]+bv0.w);
        float4 o1 = make_float4(acc[i][4]+bv1.x, acc[i][5]+bv1.y,
                                acc[i][6]+bv1.z, acc[i][7]+bv1.w);
        if (accum) {
            float4 p0 = *(const float4*)(po);
            float4 p1 = *(const float4*)(po + 4);
            o0.x += p0.x; o0.y += p0.y; o0.z += p0.z; o0.w += p0.w;
            o1.x += p1.x; o1.y += p1.y; o1.z += p1.z; o1.w += p1.w;
        }
        *(float4*)(po)     = o0;
        *(float4*)(po + 4) = o1;
    }
}

// ---------------- GATv2 edge passes ----------------
__global__ void gat_logit_kernel(const int* __restrict__ em, const float* __restrict__ att) {
    int w = (blockIdx.x << 3) + (threadIdx.x >> 5);
    if (w >= EM_N) return;
    int lane = threadIdx.x & 31;
    int s = em[w], d = em[EM_N + w];
    float4 xl = ((const float4*)(g_buf + OFF_XL + (size_t)s*HID))[lane];
    float4 xr = ((const float4*)(g_buf + OFF_XR + (size_t)d*HID))[lane];
    float4 at = ((const float4*)att)[lane];
    float ex = xl.x + xr.x; ex = ex > 0.f ? ex : 0.2f*ex;
    float ey = xl.y + xr.y; ey = ey > 0.f ? ey : 0.2f*ey;
    float ez = xl.z + xr.z; ez = ez > 0.f ? ez : 0.2f*ez;
    float ew = xl.w + xr.w; ew = ew > 0.f ? ew : 0.2f*ew;
    float p = ex*at.x + ey*at.y + ez*at.z + ew*at.w;
    p += __shfl_xor_sync(0xffffffffu, p, 1);
    p += __shfl_xor_sync(0xffffffffu, p, 2);
    p += __shfl_xor_sync(0xffffffffu, p, 4);
    if ((lane & 7) == 0) {
        int h = lane >> 3;
        g_buf[OFF_GLOGIT + (size_t)w*NH + h] = p;
        atomicMaxF(&g_buf[OFF_GMAX + (size_t)d*NH + h], p);
    }
}

__global__ void softmax_kernel(const int* __restrict__ dst, float* __restrict__ logits,
                               const float* __restrict__ mx, float* __restrict__ sm, int nE) {
    int i = blockIdx.x * blockDim.x + threadIdx.x;
    if (i >= nE*NH) return;
    int e = i >> 2, h = i & 3;
    int d = dst[e];
    float ex = __expf(logits[i] - mx[d*NH + h]);
    logits[i] = ex;
    atomicAdd(&sm[d*NH + h], ex);
}

__global__ void gat_scatter_kernel(const int* __restrict__ em) {
    int w = (blockIdx.x << 3) + (threadIdx.x >> 5);
    if (w >= EM_N) return;
    int lane = threadIdx.x & 31;
    int s = em[w], d = em[EM_N + w];
    int h = lane >> 3;
    float alpha = g_buf[OFF_GLOGIT + (size_t)w*NH + h] /
                  (g_buf[OFF_GSUM + (size_t)d*NH + h] + 1e-16f);
    float4 xl = ((const float4*)(g_buf + OFF_XL + (size_t)s*HID))[lane];
    redAdd4(g_buf + OFF_GAT + (size_t)d*HID + lane*4,
            xl.x*alpha, xl.y*alpha, xl.z*alpha, xl.w*alpha);
}

// ---------------- TransformerConv edge passes ----------------
__global__ void tr_logit_kernel(const int* __restrict__ ep, const float* __restrict__ ea,
                                const float* __restrict__ tWe) {
    int w = (blockIdx.x << 3) + (threadIdx.x >> 5);
    if (w >= EP_N) return;
    int lane = threadIdx.x & 31;
    int s = ep[w], d = ep[EP_N + w];
    float e = ea[w];
    float4 we = ((const float4*)tWe)[lane];
    float4 kv = ((const float4*)(g_buf + OFF_K + (size_t)s*HID))[lane];
    float4 qv = ((const float4*)(g_buf + OFF_Q + (size_t)d*HID))[lane];
    float p = qv.x*(kv.x + e*we.x) + qv.y*(kv.y + e*we.y)
            + qv.z*(kv.z + e*we.z) + qv.w*(kv.w + e*we.w);
    p += __shfl_xor_sync(0xffffffffu, p, 1);
    p += __shfl_xor_sync(0xffffffffu, p, 2);
    p += __shfl_xor_sync(0xffffffffu, p, 4);
    if ((lane & 7) == 0) {
        int h = lane >> 3;
        float lg = p * 0.17677669529663689f;
        g_buf[OFF_TLOGIT + (size_t)w*NH + h] = lg;
        atomicMaxF(&g_buf[OFF_TMAX + (size_t)d*NH + h], lg);
    }
}

__global__ void tr_scatter_kernel(const int* __restrict__ ep, const float* __restrict__ ea,
                                  const float* __restrict__ tWe) {
    int w = (blockIdx.x << 3) + (threadIdx.x >> 5);
    if (w >= EP_N) return;
    int lane = threadIdx.x & 31;
    int s = ep[w], d = ep[EP_N + w];
    float e = ea[w];
    int h = lane >> 3;
    float alpha = g_buf[OFF_TLOGIT + (size_t)w*NH + h] /
                  (g_buf[OFF_TSUM + (size_t)d*NH + h] + 1e-16f);
    float4 we = ((const float4*)tWe)[lane];
    float4 vv = ((const float4*)(g_buf + OFF_V + (size_t)s*HID))[lane];
    redAdd4(g_buf + OFF_TR + (size_t)d*HID + lane*4,
            (vv.x + e*we.x)*alpha, (vv.y + e*we.y)*alpha,
            (vv.z + e*we.z)*alpha, (vv.w + e*we.w)*alpha);
}

// ---------------- SAGE ----------------
__global__ void sage_scatter_kernel(const int* __restrict__ ei, const float* __restrict__ x_ball) {
    int w = (blockIdx.x << 3) + (threadIdx.x >> 5);
    if (w >= EI_N) return;
    int lane = threadIdx.x & 31;
    int s = ei[w], d = ei[EI_N + w];
    float4 xb = ((const float4*)(x_ball + (size_t)s*HID))[lane];
    redAdd4(g_buf + OFF_CTXSUM + (size_t)d*HID + lane*4, xb.x, xb.y, xb.z, xb.w);
    if (lane == 0) atomicAdd(&g_buf[OFF_CNT + d], 1.0f);
}

__global__ void mean_kernel() {
    int i = blockIdx.x * blockDim.x + threadIdx.x;
    if (i >= NC*HID) return;
    int c = i >> 7;
    g_buf[OFF_MEAN + i] = g_buf[OFF_CTXSUM + i] / fmaxf(g_buf[OFF_CNT + c], 1.0f);
}

// ---------------- LayerNorm (A + B [+ C]) ----------------
__global__ void ln_kernel(const float* __restrict__ A, const float* __restrict__ B,
                          const float* __restrict__ C, const float* __restrict__ g,
                          const float* __restrict__ b, float* __restrict__ out, int n) {
    int r = (blockIdx.x << 3) + (threadIdx.x >> 5);
    if (r >= n) return;
    int lane = threadIdx.x & 31;
    float4 p = ((const float4*)(A + (size_t)r*HID))[lane];
    float4 q = ((const float4*)(B + (size_t)r*HID))[lane];
    p.x += q.x; p.y += q.y; p.z += q.z; p.w += q.w;
    if (C) {
        float4 c4 = ((const float4*)(C + (size_t)r*HID))[lane];
        p.x += c4.x; p.y += c4.y; p.z += c4.z; p.w += c4.w;
    }
    float s = p.x + p.y + p.z + p.w;
    float sq = p.x*p.x + p.y*p.y + p.z*p.z + p.w*p.w;
    #pragma unroll
    for (int off = 16; off >= 1; off >>= 1) {
        s  += __shfl_xor_sync(0xffffffffu, s, off);
        sq += __shfl_xor_sync(0xffffffffu, sq, off);
    }
    float mu = s * (1.0f/HID);
    float var = sq * (1.0f/HID) - mu*mu;
    float rstd = rsqrtf(var + 1e-5f);
    float4 gg = ((const float4*)g)[lane];
    float4 bb = ((const float4*)b)[lane];
    float4 o;
    o.x = (p.x - mu)*rstd*gg.x + bb.x;
    o.y = (p.y - mu)*rstd*gg.y + bb.y;
    o.z = (p.z - mu)*rstd*gg.z + bb.z;
    o.w = (p.w - mu)*rstd*gg.w + bb.w;
    ((float4*)(out + (size_t)r*HID))[lane] = o;
}

__global__ void copy_player_kernel(const float* __restrict__ xp, float* __restrict__ out) {
    int i = blockIdx.x * blockDim.x + threadIdx.x;
    if (i < NP*HID/4) {
        ((float4*)out)[(size_t)(NB+NC)*HID/4 + i] = ((const float4*)xp)[i];
    }
}

// ---------------- launch ----------------
extern "C" void kernel_launch(void* const* d_in, const int* in_sizes, int n_in,
                              void* d_out, int out_size)
{
    const float* x_ball    = (const float*)d_in[0];
    const float* x_player  = (const float*)d_in[1];
    const float* x_context = (const float*)d_in[2];
    const int*   em   = (const int*)d_in[3];
    const int*   ep   = (const int*)d_in[4];
    const int*   ei   = (const int*)d_in[5];
    const float* ea_p = (const float*)d_in[6];
    const float* gWl  = (const float*)d_in[7];
    const float* gWr  = (const float*)d_in[8];
    const float* gatt = (const float*)d_in[9];
    const float* gb   = (const float*)d_in[10];
    const float* tWq  = (const float*)d_in[11];
    const float* tbq  = (const float*)d_in[12];
    const float* tWk  = (const float*)d_in[13];
    const float* tbk  = (const float*)d_in[14];
    const float* tWv  = (const float*)d_in[15];
    const float* tbv  = (const float*)d_in[16];
    const float* tWe  = (const float*)d_in[17];
    const float* tWs  = (const float*)d_in[18];
    const float* tbs  = (const float*)d_in[19];
    const float* sWl  = (const float*)d_in[20];
    const float* sbl  = (const float*)d_in[21];
    const float* sWr  = (const float*)d_in[22];
    const float* lbg  = (const float*)d_in[23];
    const float* lbb  = (const float*)d_in[24];
    const float* lcg  = (const float*)d_in[25];
    const float* lcb  = (const float*)d_in[26];
    float* out = (float*)d_out;

    float* base = nullptr;
    cudaGetSymbolAddress((void**)&base, g_buf);
    float* s_xl     = base + OFF_XL;
    float* s_xr     = base + OFF_XR;
    float* s_q      = base + OFF_Q;
    float* s_k      = base + OFF_K;
    float* s_v      = base + OFF_V;
    float* s_gat    = base + OFF_GAT;
    float* s_tr     = base + OFF_TR;
    float* s_mean   = base + OFF_MEAN;
    float* s_sage   = base + OFF_SAGE;
    float* s_glogit = base + OFF_GLOGIT;
    float* s_tlogit = base + OFF_TLOGIT;
    float* s_gmax   = base + OFF_GMAX;
    float* s_gsum   = base + OFF_GSUM;
    float* s_tmax   = base + OFF_TMAX;
    float* s_tsum   = base + OFF_TSUM;

    const int T = 256;

    cudaFuncSetAttribute(gemm128_v2, cudaFuncAttributeMaxDynamicSharedMemorySize, GEMM_SMEM);
    cudaFuncSetAttribute(big5_mma, cudaFuncAttributeMaxDynamicSharedMemorySize, SMEM_BIG5);

    // init accumulators / stat buffers
    init_kernel<<<(NB*HID + T-1)/T, T>>>(gb);

    // fused HMMA GEMM for the 5 big transforms of x_ball
    big5_mma<<<NTILE, 256, SMEM_BIG5>>>(x_ball, tWq, tWk, tWv, tWs, gWr,
                                        s_q, s_k, s_v, s_tr, s_xr,
                                        tbq, tbk, tbv, tbs);

    // small transforms on the SIMT path
    dim3 gNP((NP + 127)/128, 2), gNC((NC + 127)/128, 2);
    gemm128_v2<<<gNP, 128, GEMM_SMEM>>>(x_player, gWl, nullptr, s_xl, NP, 0);

    // GATv2: logits+max -> exp+sum -> weighted scatter
    gat_logit_kernel<<<(EM_N + 7)/8, T>>>(em, gatt);
    softmax_kernel<<<(EM_N*NH + T-1)/T, T>>>(em + EM_N, s_glogit, s_gmax, s_gsum, EM_N);
    gat_scatter_kernel<<<(EM_N + 7)/8, T>>>(em);

    // TransformerConv
    tr_logit_kernel<<<(EP_N + 7)/8, T>>>(ep, ea_p, tWe);
    softmax_kernel<<<(EP_N*NH + T-1)/T, T>>>(ep + EP_N, s_tlogit, s_tmax, s_tsum, EP_N);
    tr_scatter_kernel<<<(EP_N + 7)/8, T>>>(ep, ea_p, tWe);

    // SAGE mean
    sage_scatter_kernel<<<(EI_N + 7)/8, T>>>(ei, x_ball);
    mean_kernel<<<(NC*HID + T-1)/T, T>>>();
    gemm128_v2<<<gNC, 128, GEMM_SMEM>>>(x_context, sWr, nullptr, s_sage, NC, 0);
    gemm128_v2<<<gNC, 128, GEMM_SMEM>>>(s_mean,    sWl, sbl,     s_sage, NC, 1);

    // outputs
    ln_kernel<<<(NB + 7)/8, T>>>(s_gat, s_tr, x_ball, lbg, lbb, out, NB);
    ln_kernel<<<(NC + 7)/8, T>>>(s_sage, x_context, nullptr, lcg, lcb, out + (size_t)NB*HID, NC);
    copy_player_kernel<<<(NP*HID/4 + T-1)/T, T>>>(x_player, out);
}

// round 5
// speedup vs baseline: 2.3932x; 1.0285x over previous
#include <cuda_runtime.h>
#include <cuda_bf16.h>
#include <cstdint>

#define HID 128
#define NH 4
#define NB 60000
#define NP 2000
#define NC 4000
#define EM_N 150000
#define EP_N 300000
#define EI_N 150000
#define NTILE 469          // ceil(NB/128)

// ---- scratch layout (floats) in one big device buffer ----
#define SZ_NBH (NB*HID)
#define OFF_XL     0
#define OFF_XR     (OFF_XL + NP*HID)
#define OFF_Q      (OFF_XR + SZ_NBH)
#define OFF_K      (OFF_Q + SZ_NBH)
#define OFF_V      (OFF_K + SZ_NBH)
#define OFF_ACC    (OFF_V + SZ_NBH)      // shared GAT+TR accumulator (seeded by skip GEMM)
#define OFF_CTXSUM (OFF_ACC + SZ_NBH)
#define OFF_MEAN   (OFF_CTXSUM + NC*HID)
#define OFF_SAGE   (OFF_MEAN + NC*HID)
#define OFF_CNT    (OFF_SAGE + NC*HID)
#define OFF_GLOGIT (OFF_CNT + NC)
#define OFF_TLOGIT (OFF_GLOGIT + EM_N*NH)
#define OFF_GMAX   (OFF_TLOGIT + EP_N*NH)
#define OFF_GSUM   (OFF_GMAX + NB*NH)
#define OFF_TMAX   (OFF_GSUM + NB*NH)
#define OFF_TSUM   (OFF_TMAX + NB*NH)
#define TOTAL_SCRATCH (OFF_TSUM + NB*NH)

__device__ __align__(256) float g_buf[TOTAL_SCRATCH];

// ---------------- MMA helpers (sm_80-class, valid on plain sm_103) ----------------
__device__ __forceinline__ uint32_t smem_u32(const void* p) {
    uint32_t a;
    asm("{ .reg .u64 t; cvta.to.shared.u64 t, %1; cvt.u32.u64 %0, t; }" : "=r"(a) : "l"(p));
    return a;
}
__device__ __forceinline__ void ldsm4(uint32_t& r0, uint32_t& r1, uint32_t& r2, uint32_t& r3,
                                      uint32_t addr) {
    asm volatile("ldmatrix.sync.aligned.m8n8.x4.shared.b16 {%0,%1,%2,%3}, [%4];"
                 : "=r"(r0), "=r"(r1), "=r"(r2), "=r"(r3) : "r"(addr));
}
__device__ __forceinline__ void ldsm4t(uint32_t& r0, uint32_t& r1, uint32_t& r2, uint32_t& r3,
                                       uint32_t addr) {
    asm volatile("ldmatrix.sync.aligned.m8n8.x4.trans.shared.b16 {%0,%1,%2,%3}, [%4];"
                 : "=r"(r0), "=r"(r1), "=r"(r2), "=r"(r3) : "r"(addr));
}
__device__ __forceinline__ void mma16816(float* C, const uint32_t* A, uint32_t B0, uint32_t B1) {
    asm volatile("mma.sync.aligned.m16n8k16.row.col.f32.bf16.bf16.f32 "
                 "{%0,%1,%2,%3}, {%4,%5,%6,%7}, {%8,%9}, {%0,%1,%2,%3};"
                 : "+f"(C[0]), "+f"(C[1]), "+f"(C[2]), "+f"(C[3])
                 : "r"(A[0]), "r"(A[1]), "r"(A[2]), "r"(A[3]), "r"(B0), "r"(B1));
}

// ---------------- fused 5-output HMMA GEMM over x_ball ----------------
#define STR 136
#define SMA_H 0
#define SMA_L 34816
#define SMW_H 69632
#define SMW_L 104448
#define SMEM_BIG5 139264

__global__ void __launch_bounds__(256)
big5_mma(const float* __restrict__ xball,
         const float* __restrict__ w0, const float* __restrict__ w1,
         const float* __restrict__ w2, const float* __restrict__ w3,
         const float* __restrict__ w4,
         float* __restrict__ o0, float* __restrict__ o1, float* __restrict__ o2,
         float* __restrict__ o3, float* __restrict__ o4,
         const float* __restrict__ b0, const float* __restrict__ b1,
         const float* __restrict__ b2, const float* __restrict__ b3)
{
    extern __shared__ char smem[];
    const uint32_t sb = smem_u32(smem);
    const int tid = threadIdx.x, lane = tid & 31, warp = tid >> 5;
    const int wm = warp >> 1, wn = warp & 1;
    const int rbase = blockIdx.x * 128;

    for (int idx = tid; idx < 8192; idx += 256) {
        int row = idx >> 6, kp = idx & 63;
        int grow = rbase + row;
        float2 v = make_float2(0.f, 0.f);
        if (grow < NB) v = ((const float2*)(xball + (size_t)grow * HID))[kp];
        __nv_bfloat162 h2 = __float22bfloat162_rn(v);
        float2 lo = make_float2(v.x - __bfloat162float(h2.x),
                                v.y - __bfloat162float(h2.y));
        __nv_bfloat162 l2 = __float22bfloat162_rn(lo);
        uint32_t off = (uint32_t)(row * STR + kp * 2) * 2;
        *(uint32_t*)(smem + SMA_H + off) = *(uint32_t*)&h2;
        *(uint32_t*)(smem + SMA_L + off) = *(uint32_t*)&l2;
    }

    const float* Wg5[5]    = {w0, w1, w2, w3, w4};
    float*       outs[5]   = {o0, o1, o2, o3, o4};
    const float* biases[5] = {b0, b1, b2, b3, nullptr};

    const int gid = lane >> 2, tig = lane & 3;
    const int sub = lane >> 3, lr = lane & 7;
    const int f_r = ((sub & 1) << 3) + lr;
    const int f_c = (sub >> 1) << 3;

    for (int i = 0; i < 5; i++) {
        const float* Wg = Wg5[i];
        for (int idx = tid; idx < 8192; idx += 256) {
            int k = idx >> 6, np = idx & 63;
            float2 v = ((const float2*)(Wg + (size_t)k * HID))[np];
            __nv_bfloat162 h2 = __float22bfloat162_rn(v);
            float2 lo = make_float2(v.x - __bfloat162float(h2.x),
                                    v.y - __bfloat162float(h2.y));
            __nv_bfloat162 l2 = __float22bfloat162_rn(lo);
            uint32_t off = (uint32_t)(k * STR + np * 2) * 2;
            *(uint32_t*)(smem + SMW_H + off) = *(uint32_t*)&h2;
            *(uint32_t*)(smem + SMW_L + off) = *(uint32_t*)&l2;
        }
        __syncthreads();

        float acc[2][8][4];
        #pragma unroll
        for (int mt = 0; mt < 2; mt++)
            #pragma unroll
            for (int j = 0; j < 8; j++)
                #pragma unroll
                for (int c = 0; c < 4; c++) acc[mt][j][c] = 0.f;

        #pragma unroll
        for (int ks = 0; ks < 8; ks++) {
            const int K0 = ks * 16;
            uint32_t ah[2][4], al[2][4];
            #pragma unroll
            for (int mt = 0; mt < 2; mt++) {
                uint32_t ad = sb + SMA_H +
                    (uint32_t)((wm*32 + mt*16 + f_r) * STR + K0 + f_c) * 2;
                ldsm4(ah[mt][0], ah[mt][1], ah[mt][2], ah[mt][3], ad);
                ldsm4(al[mt][0], al[mt][1], al[mt][2], al[mt][3], ad + (SMA_L - SMA_H));
            }
            uint32_t bh[4][4], bl[4][4];
            #pragma unroll
            for (int nt = 0; nt < 4; nt++) {
                uint32_t wd = sb + SMW_H +
                    (uint32_t)((K0 + f_r) * STR + wn*64 + nt*16 + f_c) * 2;
                ldsm4t(bh[nt][0], bh[nt][1], bh[nt][2], bh[nt][3], wd);
                ldsm4t(bl[nt][0], bl[nt][1], bl[nt][2], bl[nt][3], wd + (SMW_L - SMW_H));
            }
            #pragma unroll
            for (int mt = 0; mt < 2; mt++)
                #pragma unroll
                for (int nt = 0; nt < 4; nt++)
                    #pragma unroll
                    for (int h = 0; h < 2; h++) {
                        float* C = acc[mt][nt*2 + h];
                        mma16816(C, ah[mt], bh[nt][2*h], bh[nt][2*h+1]);
                        mma16816(C, ah[mt], bl[nt][2*h], bl[nt][2*h+1]);
                        mma16816(C, al[mt], bh[nt][2*h], bh[nt][2*h+1]);
                    }
        }

        const float* bias = biases[i];
        float* outp = outs[i];
        #pragma unroll
        for (int mt = 0; mt < 2; mt++) {
            int r0g = rbase + wm*32 + mt*16 + gid;
            #pragma unroll
            for (int j = 0; j < 8; j++) {
                int cn = wn*64 + j*8 + tig*2;
                float bx = bias ? bias[cn]   : 0.f;
                float by = bias ? bias[cn+1] : 0.f;
                if (r0g < NB)
                    *(float2*)(outp + (size_t)r0g*HID + cn) =
                        make_float2(acc[mt][j][0] + bx, acc[mt][j][1] + by);
                if (r0g + 8 < NB)
                    *(float2*)(outp + (size_t)(r0g+8)*HID + cn) =
                        make_float2(acc[mt][j][2] + bx, acc[mt][j][3] + by);
            }
        }
        __syncthreads();
    }
}

// ---------------- helpers ----------------
__device__ __forceinline__ void atomicMaxF(float* addr, float val) {
    int* ia = (int*)addr;
    int old = *ia;
    while (__int_as_float(old) < val) {
        int assumed = old;
        old = atomicCAS(ia, assumed, __float_as_int(val));
        if (old == assumed) break;
    }
}
__device__ __forceinline__ void redAdd4(float* p, float a, float b, float c, float d) {
    asm volatile("red.global.add.v4.f32 [%0], {%1,%2,%3,%4};"
                 :: "l"(p), "f"(a), "f"(b), "f"(c), "f"(d) : "memory");
}

// ---------------- init (small stat buffers + ctxsum only) ----------------
__global__ void init_kernel() {
    int i = blockIdx.x * blockDim.x + threadIdx.x;
    if (i < NB*NH) {
        float ninf = __int_as_float(0xff800000);
        g_buf[OFF_GMAX + i] = ninf;
        g_buf[OFF_TMAX + i] = ninf;
        g_buf[OFF_GSUM + i] = 0.f;
        g_buf[OFF_TSUM + i] = 0.f;
    }
    if (i < NC*HID) g_buf[OFF_CTXSUM + i] = 0.f;
    if (i < NC) g_buf[OFF_CNT + i] = 0.f;
}

// ---------------- SIMT GEMM (small matrices only) ----------------
#define AS_STRIDE 132
#define GEMM_SMEM ((128*AS_STRIDE + 128*64) * 4)

__global__ void __launch_bounds__(128)
gemm128_v2(const float* __restrict__ A, const float* __restrict__ W,
           const float* __restrict__ bias, float* __restrict__ out,
           int nrows, int accum)
{
    extern __shared__ float sm[];
    float* As = sm;
    float* Ws = sm + 128*AS_STRIDE;
    const int colHalf = blockIdx.y;
    const int tid = threadIdx.x;
    const int rbase = blockIdx.x * 128;

    for (int idx = tid; idx < 128*16; idx += 128) {
        int k = idx >> 4, c4 = idx & 15;
        ((float4*)(Ws + k*64))[c4] =
            ((const float4*)(W + (size_t)k*HID + colHalf*64))[c4];
    }
    for (int idx = tid; idx < 128*32; idx += 128) {
        int r = idx >> 5, c4 = idx & 31;
        int gr = rbase + r;
        float4 v = make_float4(0.f, 0.f, 0.f, 0.f);
        if (gr < nrows) v = ((const float4*)(A + (size_t)gr*HID))[c4];
        *(float4*)(As + r*AS_STRIDE + c4*4) = v;
    }
    __syncthreads();

    const int tc = tid & 7, tr = tid >> 3;
    float acc[8][8];
    #pragma unroll
    for (int i = 0; i < 8; i++)
        #pragma unroll
        for (int j = 0; j < 8; j++) acc[i][j] = 0.f;

    #pragma unroll 4
    for (int k4 = 0; k4 < 32; k4++) {
        float4 a4[8];
        #pragma unroll
        for (int i = 0; i < 8; i++)
            a4[i] = *(const float4*)(As + (tr*8 + i)*AS_STRIDE + k4*4);
        #pragma unroll
        for (int kk = 0; kk < 4; kk++) {
            const float* wrow = Ws + (k4*4 + kk)*64 + tc*8;
            float4 w0 = *(const float4*)(wrow);
            float4 w1 = *(const float4*)(wrow + 4);
            #pragma unroll
            for (int i = 0; i < 8; i++) {
                float av = (kk == 0) ? a4[i].x : (kk == 1) ? a4[i].y
                         : (kk == 2) ? a4[i].z : a4[i].w;
                acc[i][0] += av * w0.x; acc[i][1] += av * w0.y;
                acc[i][2] += av * w0.z; acc[i][3] += av * w0.w;
                acc[i][4] += av * w1.x; acc[i][5] += av * w1.y;
                acc[i][6] += av * w1.z; acc[i][7] += av * w1.w;
            }
        }
    }

    float4 bv0 = make_float4(0.f,0.f,0.f,0.f), bv1 = bv0;
    if (bias) {
        bv0 = *(const float4*)(bias + colHalf*64 + tc*8);
        bv1 = *(const float4*)(bias + colHalf*64 + tc*8 + 4);
    }
    #pragma unroll
    for (int i = 0; i < 8; i++) {
        int gr = rbase + tr*8 + i;
        if (gr >= nrows) break;
        float* po = out + (size_t)gr*HID + colHalf*64 + tc*8;
        float4 o0 = make_float4(acc[i][0]+bv0.x, acc[i][1]+bv0.y,
                                acc[i][2]+bv0.z, acc[i][3]+bv0.w);
        float4 o1 = make_float4(acc[i][4]+bv1.x, acc[i][5]+bv1.y,
                                acc[i][6]+bv1.z, acc[i][7]+bv1.w);
        if (accum) {
            float4 p0 = *(const float4*)(po);
            float4 p1 = *(const float4*)(po + 4);
            o0.x += p0.x; o0.y += p0.y; o0.z += p0.z; o0.w += p0.w;
            o1.x += p1.x; o1.y += p1.y; o1.z += p1.z; o1.w += p1.w;
        }
        *(float4*)(po)     = o0;
        *(float4*)(po + 4) = o1;
    }
}

// ================= edge kernels: 4 edges per warp, batched prefetch =================
// lanes 0-3 load src[e0+j], lanes 4-7 load dst[e0+j]; shfl-broadcast.

__global__ void __launch_bounds__(256)
gat_logit_kernel(const int* __restrict__ em, const float* __restrict__ att) {
    int w = blockIdx.x * 8 + (threadIdx.x >> 5);
    int e0 = w << 2;
    if (e0 >= EM_N) return;
    int lane = threadIdx.x & 31;
    int idx = 0;
    if (lane < 8) {
        int e = e0 + (lane & 3);
        if (e < EM_N) idx = em[(lane & 4) ? EM_N + e : e];
    }
    int ss[4], dd[4];
    #pragma unroll
    for (int j = 0; j < 4; j++) {
        ss[j] = __shfl_sync(0xffffffffu, idx, j);
        dd[j] = __shfl_sync(0xffffffffu, idx, 4 + j);
    }
    float4 at = ((const float4*)att)[lane];
    float4 xlv[4], xrv[4];
    #pragma unroll
    for (int j = 0; j < 4; j++) {
        if (e0 + j < EM_N) {
            xlv[j] = ((const float4*)(g_buf + OFF_XL + (size_t)ss[j]*HID))[lane];
            xrv[j] = ((const float4*)(g_buf + OFF_XR + (size_t)dd[j]*HID))[lane];
        }
    }
    #pragma unroll
    for (int j = 0; j < 4; j++) {
        if (e0 + j >= EM_N) break;
        float ex = xlv[j].x + xrv[j].x; ex = ex > 0.f ? ex : 0.2f*ex;
        float ey = xlv[j].y + xrv[j].y; ey = ey > 0.f ? ey : 0.2f*ey;
        float ez = xlv[j].z + xrv[j].z; ez = ez > 0.f ? ez : 0.2f*ez;
        float ew = xlv[j].w + xrv[j].w; ew = ew > 0.f ? ew : 0.2f*ew;
        float p = ex*at.x + ey*at.y + ez*at.z + ew*at.w;
        p += __shfl_xor_sync(0xffffffffu, p, 1);
        p += __shfl_xor_sync(0xffffffffu, p, 2);
        p += __shfl_xor_sync(0xffffffffu, p, 4);
        if ((lane & 7) == 0) {
            int h = lane >> 3;
            g_buf[OFF_GLOGIT + (size_t)(e0 + j)*NH + h] = p;
            atomicMaxF(&g_buf[OFF_GMAX + (size_t)dd[j]*NH + h], p);
        }
    }
}

__global__ void __launch_bounds__(256)
tr_logit_kernel(const int* __restrict__ ep, const float* __restrict__ ea,
                const float* __restrict__ tWe) {
    int w = blockIdx.x * 8 + (threadIdx.x >> 5);
    int e0 = w << 2;
    if (e0 >= EP_N) return;
    int lane = threadIdx.x & 31;
    int idx = 0;
    if (lane < 8) {
        int e = e0 + (lane & 3);
        if (e < EP_N) idx = ep[(lane & 4) ? EP_N + e : e];
    }
    float eav = 0.f;
    if (lane >= 8 && lane < 12) {
        int e = e0 + (lane & 3);
        if (e < EP_N) eav = ea[e];
    }
    int ss[4], dd[4]; float ev[4];
    #pragma unroll
    for (int j = 0; j < 4; j++) {
        ss[j] = __shfl_sync(0xffffffffu, idx, j);
        dd[j] = __shfl_sync(0xffffffffu, idx, 4 + j);
        ev[j] = __shfl_sync(0xffffffffu, eav, 8 + j);
    }
    float4 we = ((const float4*)tWe)[lane];
    float4 kv[4], qv[4];
    #pragma unroll
    for (int j = 0; j < 4; j++) {
        if (e0 + j < EP_N) {
            kv[j] = ((const float4*)(g_buf + OFF_K + (size_t)ss[j]*HID))[lane];
            qv[j] = ((const float4*)(g_buf + OFF_Q + (size_t)dd[j]*HID))[lane];
        }
    }
    #pragma unroll
    for (int j = 0; j < 4; j++) {
        if (e0 + j >= EP_N) break;
        float e = ev[j];
        float p = qv[j].x*(kv[j].x + e*we.x) + qv[j].y*(kv[j].y + e*we.y)
                + qv[j].z*(kv[j].z + e*we.z) + qv[j].w*(kv[j].w + e*we.w);
        p += __shfl_xor_sync(0xffffffffu, p, 1);
        p += __shfl_xor_sync(0xffffffffu, p, 2);
        p += __shfl_xor_sync(0xffffffffu, p, 4);
        if ((lane & 7) == 0) {
            int h = lane >> 3;
            float lg = p * 0.17677669529663689f;
            g_buf[OFF_TLOGIT + (size_t)(e0 + j)*NH + h] = lg;
            atomicMaxF(&g_buf[OFF_TMAX + (size_t)dd[j]*NH + h], lg);
        }
    }
}

// fused softmax pass for both edge sets
__global__ void softmax2_kernel(const int* __restrict__ emdst, const int* __restrict__ epdst) {
    int i = blockIdx.x * blockDim.x + threadIdx.x;
    if (i < EM_N*NH) {
        int e = i >> 2, h = i & 3;
        int d = emdst[e];
        float ex = __expf(g_buf[OFF_GLOGIT + i] - g_buf[OFF_GMAX + d*NH + h]);
        g_buf[OFF_GLOGIT + i] = ex;
        atomicAdd(&g_buf[OFF_GSUM + d*NH + h], ex);
    } else if (i < (EM_N + EP_N)*NH) {
        int k = i - EM_N*NH;
        int e = k >> 2, h = k & 3;
        int d = epdst[e];
        float ex = __expf(g_buf[OFF_TLOGIT + k] - g_buf[OFF_TMAX + d*NH + h]);
        g_buf[OFF_TLOGIT + k] = ex;
        atomicAdd(&g_buf[OFF_TSUM + d*NH + h], ex);
    }
}

__global__ void __launch_bounds__(256)
gat_scatter_kernel(const int* __restrict__ em) {
    int w = blockIdx.x * 8 + (threadIdx.x >> 5);
    int e0 = w << 2;
    if (e0 >= EM_N) return;
    int lane = threadIdx.x & 31;
    int idx = 0;
    if (lane < 8) {
        int e = e0 + (lane & 3);
        if (e < EM_N) idx = em[(lane & 4) ? EM_N + e : e];
    }
    int ss[4], dd[4];
    #pragma unroll
    for (int j = 0; j < 4; j++) {
        ss[j] = __shfl_sync(0xffffffffu, idx, j);
        dd[j] = __shfl_sync(0xffffffffu, idx, 4 + j);
    }
    int h = lane >> 3;
    float lg[4], sm[4]; float4 xl[4];
    #pragma unroll
    for (int j = 0; j < 4; j++) {
        if (e0 + j < EM_N) {
            lg[j] = g_buf[OFF_GLOGIT + (size_t)(e0 + j)*NH + h];
            sm[j] = g_buf[OFF_GSUM + (size_t)dd[j]*NH + h];
            xl[j] = ((const float4*)(g_buf + OFF_XL + (size_t)ss[j]*HID))[lane];
        }
    }
    #pragma unroll
    for (int j = 0; j < 4; j++) {
        if (e0 + j >= EM_N) break;
        float alpha = lg[j] / (sm[j] + 1e-16f);
        redAdd4(g_buf + OFF_ACC + (size_t)dd[j]*HID + lane*4,
                xl[j].x*alpha, xl[j].y*alpha, xl[j].z*alpha, xl[j].w*alpha);
    }
}

__global__ void __launch_bounds__(256)
tr_scatter_kernel(const int* __restrict__ ep, const float* __restrict__ ea,
                  const float* __restrict__ tWe) {
    int w = blockIdx.x * 8 + (threadIdx.x >> 5);
    int e0 = w << 2;
    if (e0 >= EP_N) return;
    int lane = threadIdx.x & 31;
    int idx = 0;
    if (lane < 8) {
        int e = e0 + (lane & 3);
        if (e < EP_N) idx = ep[(lane & 4) ? EP_N + e : e];
    }
    float eav = 0.f;
    if (lane >= 8 && lane < 12) {
        int e = e0 + (lane & 3);
        if (e < EP_N) eav = ea[e];
    }
    int ss[4], dd[4]; float ev[4];
    #pragma unroll
    for (int j = 0; j < 4; j++) {
        ss[j] = __shfl_sync(0xffffffffu, idx, j);
        dd[j] = __shfl_sync(0xffffffffu, idx, 4 + j);
        ev[j] = __shfl_sync(0xffffffffu, eav, 8 + j);
    }
    int h = lane >> 3;
    float4 we = ((const float4*)tWe)[lane];
    float lg[4], sm[4]; float4 vv[4];
    #pragma unroll
    for (int j = 0; j < 4; j++) {
        if (e0 + j < EP_N) {
            lg[j] = g_buf[OFF_TLOGIT + (size_t)(e0 + j)*NH + h];
            sm[j] = g_buf[OFF_TSUM + (size_t)dd[j]*NH + h];
            vv[j] = ((const float4*)(g_buf + OFF_V + (size_t)ss[j]*HID))[lane];
        }
    }
    #pragma unroll
    for (int j = 0; j < 4; j++) {
        if (e0 + j >= EP_N) break;
        float alpha = lg[j] / (sm[j] + 1e-16f);
        float e = ev[j];
        redAdd4(g_buf + OFF_ACC + (size_t)dd[j]*HID + lane*4,
                (vv[j].x + e*we.x)*alpha, (vv[j].y + e*we.y)*alpha,
                (vv[j].z + e*we.z)*alpha, (vv[j].w + e*we.w)*alpha);
    }
}

__global__ void __launch_bounds__(256)
sage_scatter_kernel(const int* __restrict__ ei, const float* __restrict__ x_ball) {
    int w = blockIdx.x * 8 + (threadIdx.x >> 5);
    int e0 = w << 2;
    if (e0 >= EI_N) return;
    int lane = threadIdx.x & 31;
    int idx = 0;
    if (lane < 8) {
        int e = e0 + (lane & 3);
        if (e < EI_N) idx = ei[(lane & 4) ? EI_N + e : e];
    }
    int ss[4], dd[4];
    #pragma unroll
    for (int j = 0; j < 4; j++) {
        ss[j] = __shfl_sync(0xffffffffu, idx, j);
        dd[j] = __shfl_sync(0xffffffffu, idx, 4 + j);
    }
    float4 xb[4];
    #pragma unroll
    for (int j = 0; j < 4; j++)
        if (e0 + j < EI_N)
            xb[j] = ((const float4*)(x_ball + (size_t)ss[j]*HID))[lane];
    #pragma unroll
    for (int j = 0; j < 4; j++) {
        if (e0 + j >= EI_N) break;
        redAdd4(g_buf + OFF_CTXSUM + (size_t)dd[j]*HID + lane*4,
                xb[j].x, xb[j].y, xb[j].z, xb[j].w);
        if (lane == 0) atomicAdd(&g_buf[OFF_CNT + dd[j]], 1.0f);
    }
}

__global__ void mean_kernel() {
    int i = blockIdx.x * blockDim.x + threadIdx.x;
    if (i >= NC*HID) return;
    int c = i >> 7;
    g_buf[OFF_MEAN + i] = g_buf[OFF_CTXSUM + i] / fmaxf(g_buf[OFF_CNT + c], 1.0f);
}

// ---------------- LayerNorm: out = LN(A + B [+ bcast]) ----------------
__global__ void ln_kernel(const float* __restrict__ A, const float* __restrict__ B,
                          const float* __restrict__ bcast, const float* __restrict__ g,
                          const float* __restrict__ b, float* __restrict__ out, int n) {
    int r = (blockIdx.x << 3) + (threadIdx.x >> 5);
    if (r >= n) return;
    int lane = threadIdx.x & 31;
    float4 p = ((const float4*)(A + (size_t)r*HID))[lane];
    float4 q = ((const float4*)(B + (size_t)r*HID))[lane];
    p.x += q.x; p.y += q.y; p.z += q.z; p.w += q.w;
    if (bcast) {
        float4 c4 = ((const float4*)bcast)[lane];
        p.x += c4.x; p.y += c4.y; p.z += c4.z; p.w += c4.w;
    }
    float s = p.x + p.y + p.z + p.w;
    float sq = p.x*p.x + p.y*p.y + p.z*p.z + p.w*p.w;
    #pragma unroll
    for (int off = 16; off >= 1; off >>= 1) {
        s  += __shfl_xor_sync(0xffffffffu, s, off);
        sq += __shfl_xor_sync(0xffffffffu, sq, off);
    }
    float mu = s * (1.0f/HID);
    float var = sq * (1.0f/HID) - mu*mu;
    float rstd = rsqrtf(var + 1e-5f);
    float4 gg = ((const float4*)g)[lane];
    float4 bb = ((const float4*)b)[lane];
    float4 o;
    o.x = (p.x - mu)*rstd*gg.x + bb.x;
    o.y = (p.y - mu)*rstd*gg.y + bb.y;
    o.z = (p.z - mu)*rstd*gg.z + bb.z;
    o.w = (p.w - mu)*rstd*gg.w + bb.w;
    ((float4*)(out + (size_t)r*HID))[lane] = o;
}

// ---------------- launch ----------------
extern "C" void kernel_launch(void* const* d_in, const int* in_sizes, int n_in,
                              void* d_out, int out_size)
{
    const float* x_ball    = (const float*)d_in[0];
    const float* x_player  = (const float*)d_in[1];
    const float* x_context = (const float*)d_in[2];
    const int*   em   = (const int*)d_in[3];
    const int*   ep   = (const int*)d_in[4];
    const int*   ei   = (const int*)d_in[5];
    const float* ea_p = (const float*)d_in[6];
    const float* gWl  = (const float*)d_in[7];
    const float* gWr  = (const float*)d_in[8];
    const float* gatt = (const float*)d_in[9];
    const float* gb   = (const float*)d_in[10];
    const float* tWq  = (const float*)d_in[11];
    const float* tbq  = (const float*)d_in[12];
    const float* tWk  = (const float*)d_in[13];
    const float* tbk  = (const float*)d_in[14];
    const float* tWv  = (const float*)d_in[15];
    const float* tbv  = (const float*)d_in[16];
    const float* tWe  = (const float*)d_in[17];
    const float* tWs  = (const float*)d_in[18];
    const float* tbs  = (const float*)d_in[19];
    const float* sWl  = (const float*)d_in[20];
    const float* sbl  = (const float*)d_in[21];
    const float* sWr  = (const float*)d_in[22];
    const float* lbg  = (const float*)d_in[23];
    const float* lbb  = (const float*)d_in[24];
    const float* lcg  = (const float*)d_in[25];
    const float* lcb  = (const float*)d_in[26];
    float* out = (float*)d_out;

    float* base = nullptr;
    cudaGetSymbolAddress((void**)&base, g_buf);
    float* s_xl   = base + OFF_XL;
    float* s_xr   = base + OFF_XR;
    float* s_q    = base + OFF_Q;
    float* s_k    = base + OFF_K;
    float* s_v    = base + OFF_V;
    float* s_acc  = base + OFF_ACC;
    float* s_mean = base + OFF_MEAN;
    float* s_sage = base + OFF_SAGE;

    const int T = 256;

    cudaFuncSetAttribute(gemm128_v2, cudaFuncAttributeMaxDynamicSharedMemorySize, GEMM_SMEM);
    cudaFuncSetAttribute(big5_mma, cudaFuncAttributeMaxDynamicSharedMemorySize, SMEM_BIG5);

    // init small stat buffers
    init_kernel<<<(NC*HID + T-1)/T, T>>>();

    // fused HMMA GEMM: q,k,v,(skip->acc),xr
    big5_mma<<<NTILE, 256, SMEM_BIG5>>>(x_ball, tWq, tWk, tWv, tWs, gWr,
                                        s_q, s_k, s_v, s_acc, s_xr,
                                        tbq, tbk, tbv, tbs);

    // small transforms on the SIMT path
    dim3 gNP((NP + 127)/128, 2), gNC((NC + 127)/128, 2);
    gemm128_v2<<<gNP, 128, GEMM_SMEM>>>(x_player, gWl, nullptr, s_xl, NP, 0);

    // logits + running max  (4 edges / warp, 32 edges / block)
    gat_logit_kernel<<<(EM_N + 31)/32, T>>>(em, gatt);
    tr_logit_kernel<<<(EP_N + 31)/32, T>>>(ep, ea_p, tWe);

    // fused exp + segment-sum for both edge sets
    softmax2_kernel<<<((EM_N + EP_N)*NH + T-1)/T, T>>>(em + EM_N, ep + EP_N);

    // weighted scatters into the shared ACC buffer
    gat_scatter_kernel<<<(EM_N + 31)/32, T>>>(em);
    tr_scatter_kernel<<<(EP_N + 31)/32, T>>>(ep, ea_p, tWe);

    // SAGE mean path
    sage_scatter_kernel<<<(EI_N + 31)/32, T>>>(ei, x_ball);
    mean_kernel<<<(NC*HID + T-1)/T, T>>>();
    gemm128_v2<<<gNC, 128, GEMM_SMEM>>>(x_context, sWr, nullptr, s_sage, NC, 0);
    gemm128_v2<<<gNC, 128, GEMM_SMEM>>>(s_mean,    sWl, sbl,     s_sage, NC, 1);

    // outputs: ball = LN(acc + x_ball + g_b), ctx = LN(sage + x_ctx), player passthrough
    ln_kernel<<<(NB + 7)/8, T>>>(s_acc, x_ball, gb, lbg, lbb, out, NB);
    ln_kernel<<<(NC + 7)/8, T>>>(s_sage, x_context, nullptr, lcg, lcb, out + (size_t)NB*HID, NC);
    cudaMemcpyAsync(out + (size_t)(NB+NC)*HID, x_player, (size_t)NP*HID*sizeof(float),
                    cudaMemcpyDeviceToDevice);
}

// round 6
// speedup vs baseline: 2.8063x; 1.1726x over previous
#include <cuda_runtime.h>
#include <cuda_bf16.h>
#include <cstdint>

#define HID 128
#define NH 4
#define NB 60000
#define NP 2000
#define NC 4000
#define EM_N 150000
#define EP_N 300000
#define EI_N 150000
#define NTILE 469          // ceil(NB/128)

// block counts for merged edge passes (4 edges/warp, 8 warps/block => 32 edges/block)
#define BG1 ((EM_N/4 + 7)/8)      // 4688
#define BT1 ((EP_N/4 + 7)/8)      // 9375
#define BS1 ((EI_N/4 + 7)/8)      // 4688
#define PASS1_GRID (BG1 + BT1 + BS1)
#define MEAN_BLKS ((NC*HID + 255)/256)
#define PASS2_GRID (BG1 + BT1 + MEAN_BLKS)

// ---- scratch layout (floats) in one big device buffer ----
#define SZ_NBH (NB*HID)
#define OFF_XL     0
#define OFF_XR     (OFF_XL + NP*HID)
#define OFF_Q      (OFF_XR + SZ_NBH)
#define OFF_K      (OFF_Q + SZ_NBH)
#define OFF_V      (OFF_K + SZ_NBH)
#define OFF_ACC    (OFF_V + SZ_NBH)      // shared GAT+TR accumulator (seeded by skip GEMM)
#define OFF_CTXSUM (OFF_ACC + SZ_NBH)
#define OFF_MEAN   (OFF_CTXSUM + NC*HID)
#define OFF_SAGE   (OFF_MEAN + NC*HID)
#define OFF_CNT    (OFF_SAGE + NC*HID)
#define OFF_GLOGIT (OFF_CNT + NC)
#define OFF_TLOGIT (OFF_GLOGIT + EM_N*NH)
#define OFF_GSUM   (OFF_TLOGIT + EP_N*NH)
#define OFF_TSUM   (OFF_GSUM + NB*NH)
#define TOTAL_SCRATCH (OFF_TSUM + NB*NH)

__device__ __align__(256) float g_buf[TOTAL_SCRATCH];

// ---------------- MMA helpers (sm_80-class, valid on plain sm_103) ----------------
__device__ __forceinline__ uint32_t smem_u32(const void* p) {
    uint32_t a;
    asm("{ .reg .u64 t; cvta.to.shared.u64 t, %1; cvt.u32.u64 %0, t; }" : "=r"(a) : "l"(p));
    return a;
}
__device__ __forceinline__ void ldsm4(uint32_t& r0, uint32_t& r1, uint32_t& r2, uint32_t& r3,
                                      uint32_t addr) {
    asm volatile("ldmatrix.sync.aligned.m8n8.x4.shared.b16 {%0,%1,%2,%3}, [%4];"
                 : "=r"(r0), "=r"(r1), "=r"(r2), "=r"(r3) : "r"(addr));
}
__device__ __forceinline__ void ldsm4t(uint32_t& r0, uint32_t& r1, uint32_t& r2, uint32_t& r3,
                                       uint32_t addr) {
    asm volatile("ldmatrix.sync.aligned.m8n8.x4.trans.shared.b16 {%0,%1,%2,%3}, [%4];"
                 : "=r"(r0), "=r"(r1), "=r"(r2), "=r"(r3) : "r"(addr));
}
__device__ __forceinline__ void mma16816(float* C, const uint32_t* A, uint32_t B0, uint32_t B1) {
    asm volatile("mma.sync.aligned.m16n8k16.row.col.f32.bf16.bf16.f32 "
                 "{%0,%1,%2,%3}, {%4,%5,%6,%7}, {%8,%9}, {%0,%1,%2,%3};"
                 : "+f"(C[0]), "+f"(C[1]), "+f"(C[2]), "+f"(C[3])
                 : "r"(A[0]), "r"(A[1]), "r"(A[2]), "r"(A[3]), "r"(B0), "r"(B1));
}

// ---------------- fused 5-output HMMA GEMM over x_ball ----------------
#define STR 136
#define SMA_H 0
#define SMA_L 34816
#define SMW_H 69632
#define SMW_L 104448
#define SMEM_BIG5 139264

__global__ void __launch_bounds__(256)
big5_mma(const float* __restrict__ xball,
         const float* __restrict__ w0, const float* __restrict__ w1,
         const float* __restrict__ w2, const float* __restrict__ w3,
         const float* __restrict__ w4,
         float* __restrict__ o0, float* __restrict__ o1, float* __restrict__ o2,
         float* __restrict__ o3, float* __restrict__ o4,
         const float* __restrict__ b0, const float* __restrict__ b1,
         const float* __restrict__ b2, const float* __restrict__ b3)
{
    extern __shared__ char smem[];
    const uint32_t sb = smem_u32(smem);
    const int tid = threadIdx.x, lane = tid & 31, warp = tid >> 5;
    const int wm = warp >> 1, wn = warp & 1;
    const int rbase = blockIdx.x * 128;

    for (int idx = tid; idx < 8192; idx += 256) {
        int row = idx >> 6, kp = idx & 63;
        int grow = rbase + row;
        float2 v = make_float2(0.f, 0.f);
        if (grow < NB) v = ((const float2*)(xball + (size_t)grow * HID))[kp];
        __nv_bfloat162 h2 = __float22bfloat162_rn(v);
        float2 lo = make_float2(v.x - __bfloat162float(h2.x),
                                v.y - __bfloat162float(h2.y));
        __nv_bfloat162 l2 = __float22bfloat162_rn(lo);
        uint32_t off = (uint32_t)(row * STR + kp * 2) * 2;
        *(uint32_t*)(smem + SMA_H + off) = *(uint32_t*)&h2;
        *(uint32_t*)(smem + SMA_L + off) = *(uint32_t*)&l2;
    }

    const float* Wg5[5]    = {w0, w1, w2, w3, w4};
    float*       outs[5]   = {o0, o1, o2, o3, o4};
    const float* biases[5] = {b0, b1, b2, b3, nullptr};

    const int gid = lane >> 2, tig = lane & 3;
    const int sub = lane >> 3, lr = lane & 7;
    const int f_r = ((sub & 1) << 3) + lr;
    const int f_c = (sub >> 1) << 3;

    for (int i = 0; i < 5; i++) {
        const float* Wg = Wg5[i];
        for (int idx = tid; idx < 8192; idx += 256) {
            int k = idx >> 6, np = idx & 63;
            float2 v = ((const float2*)(Wg + (size_t)k * HID))[np];
            __nv_bfloat162 h2 = __float22bfloat162_rn(v);
            float2 lo = make_float2(v.x - __bfloat162float(h2.x),
                                    v.y - __bfloat162float(h2.y));
            __nv_bfloat162 l2 = __float22bfloat162_rn(lo);
            uint32_t off = (uint32_t)(k * STR + np * 2) * 2;
            *(uint32_t*)(smem + SMW_H + off) = *(uint32_t*)&h2;
            *(uint32_t*)(smem + SMW_L + off) = *(uint32_t*)&l2;
        }
        __syncthreads();

        float acc[2][8][4];
        #pragma unroll
        for (int mt = 0; mt < 2; mt++)
            #pragma unroll
            for (int j = 0; j < 8; j++)
                #pragma unroll
                for (int c = 0; c < 4; c++) acc[mt][j][c] = 0.f;

        #pragma unroll
        for (int ks = 0; ks < 8; ks++) {
            const int K0 = ks * 16;
            uint32_t ah[2][4], al[2][4];
            #pragma unroll
            for (int mt = 0; mt < 2; mt++) {
                uint32_t ad = sb + SMA_H +
                    (uint32_t)((wm*32 + mt*16 + f_r) * STR + K0 + f_c) * 2;
                ldsm4(ah[mt][0], ah[mt][1], ah[mt][2], ah[mt][3], ad);
                ldsm4(al[mt][0], al[mt][1], al[mt][2], al[mt][3], ad + (SMA_L - SMA_H));
            }
            uint32_t bh[4][4], bl[4][4];
            #pragma unroll
            for (int nt = 0; nt < 4; nt++) {
                uint32_t wd = sb + SMW_H +
                    (uint32_t)((K0 + f_r) * STR + wn*64 + nt*16 + f_c) * 2;
                ldsm4t(bh[nt][0], bh[nt][1], bh[nt][2], bh[nt][3], wd);
                ldsm4t(bl[nt][0], bl[nt][1], bl[nt][2], bl[nt][3], wd + (SMW_L - SMW_H));
            }
            #pragma unroll
            for (int mt = 0; mt < 2; mt++)
                #pragma unroll
                for (int nt = 0; nt < 4; nt++)
                    #pragma unroll
                    for (int h = 0; h < 2; h++) {
                        float* C = acc[mt][nt*2 + h];
                        mma16816(C, ah[mt], bh[nt][2*h], bh[nt][2*h+1]);
                        mma16816(C, ah[mt], bl[nt][2*h], bl[nt][2*h+1]);
                        mma16816(C, al[mt], bh[nt][2*h], bh[nt][2*h+1]);
                    }
        }

        const float* bias = biases[i];
        float* outp = outs[i];
        #pragma unroll
        for (int mt = 0; mt < 2; mt++) {
            int r0g = rbase + wm*32 + mt*16 + gid;
            #pragma unroll
            for (int j = 0; j < 8; j++) {
                int cn = wn*64 + j*8 + tig*2;
                float bx = bias ? bias[cn]   : 0.f;
                float by = bias ? bias[cn+1] : 0.f;
                if (r0g < NB)
                    *(float2*)(outp + (size_t)r0g*HID + cn) =
                        make_float2(acc[mt][j][0] + bx, acc[mt][j][1] + by);
                if (r0g + 8 < NB)
                    *(float2*)(outp + (size_t)(r0g+8)*HID + cn) =
                        make_float2(acc[mt][j][2] + bx, acc[mt][j][3] + by);
            }
        }
        __syncthreads();
    }
}

// ---------------- helpers ----------------
__device__ __forceinline__ void redAdd4(float* p, float a, float b, float c, float d) {
    asm volatile("red.global.add.v4.f32 [%0], {%1,%2,%3,%4};"
                 :: "l"(p), "f"(a), "f"(b), "f"(c), "f"(d) : "memory");
}

// ---------------- init (sum buffers + ctxsum + cnt) ----------------
__global__ void init_kernel() {
    int i = blockIdx.x * blockDim.x + threadIdx.x;
    if (i < NB*NH) {
        g_buf[OFF_GSUM + i] = 0.f;
        g_buf[OFF_TSUM + i] = 0.f;
    }
    if (i < NC*HID) g_buf[OFF_CTXSUM + i] = 0.f;
    if (i < NC) g_buf[OFF_CNT + i] = 0.f;
}

// ---------------- SIMT GEMM (small matrices only) ----------------
#define AS_STRIDE 132
#define GEMM_SMEM ((128*AS_STRIDE + 128*64) * 4)

__global__ void __launch_bounds__(128)
gemm128_v2(const float* __restrict__ A, const float* __restrict__ W,
           const float* __restrict__ bias, float* __restrict__ out,
           int nrows, int accum)
{
    extern __shared__ float sm[];
    float* As = sm;
    float* Ws = sm + 128*AS_STRIDE;
    const int colHalf = blockIdx.y;
    const int tid = threadIdx.x;
    const int rbase = blockIdx.x * 128;

    for (int idx = tid; idx < 128*16; idx += 128) {
        int k = idx >> 4, c4 = idx & 15;
        ((float4*)(Ws + k*64))[c4] =
            ((const float4*)(W + (size_t)k*HID + colHalf*64))[c4];
    }
    for (int idx = tid; idx < 128*32; idx += 128) {
        int r = idx >> 5, c4 = idx & 31;
        int gr = rbase + r;
        float4 v = make_float4(0.f, 0.f, 0.f, 0.f);
        if (gr < nrows) v = ((const float4*)(A + (size_t)gr*HID))[c4];
        *(float4*)(As + r*AS_STRIDE + c4*4) = v;
    }
    __syncthreads();

    const int tc = tid & 7, tr = tid >> 3;
    float acc[8][8];
    #pragma unroll
    for (int i = 0; i < 8; i++)
        #pragma unroll
        for (int j = 0; j < 8; j++) acc[i][j] = 0.f;

    #pragma unroll 4
    for (int k4 = 0; k4 < 32; k4++) {
        float4 a4[8];
        #pragma unroll
        for (int i = 0; i < 8; i++)
            a4[i] = *(const float4*)(As + (tr*8 + i)*AS_STRIDE + k4*4);
        #pragma unroll
        for (int kk = 0; kk < 4; kk++) {
            const float* wrow = Ws + (k4*4 + kk)*64 + tc*8;
            float4 w0 = *(const float4*)(wrow);
            float4 w1 = *(const float4*)(wrow + 4);
            #pragma unroll
            for (int i = 0; i < 8; i++) {
                float av = (kk == 0) ? a4[i].x : (kk == 1) ? a4[i].y
                         : (kk == 2) ? a4[i].z : a4[i].w;
                acc[i][0] += av * w0.x; acc[i][1] += av * w0.y;
                acc[i][2] += av * w0.z; acc[i][3] += av * w0.w;
                acc[i][4] += av * w1.x; acc[i][5] += av * w1.y;
                acc[i][6] += av * w1.z; acc[i][7] += av * w1.w;
            }
        }
    }

    float4 bv0 = make_float4(0.f,0.f,0.f,0.f), bv1 = bv0;
    if (bias) {
        bv0 = *(const float4*)(bias + colHalf*64 + tc*8);
        bv1 = *(const float4*)(bias + colHalf*64 + tc*8 + 4);
    }
    #pragma unroll
    for (int i = 0; i < 8; i++) {
        int gr = rbase + tr*8 + i;
        if (gr >= nrows) break;
        float* po = out + (size_t)gr*HID + colHalf*64 + tc*8;
        float4 o0 = make_float4(acc[i][0]+bv0.x, acc[i][1]+bv0.y,
                                acc[i][2]+bv0.z, acc[i][3]+bv0.w);
        float4 o1 = make_float4(acc[i][4]+bv1.x, acc[i][5]+bv1.y,
                                acc[i][6]+bv1.z, acc[i][7]+bv1.w);
        if (accum) {
            float4 p0 = *(const float4*)(po);
            float4 p1 = *(const float4*)(po + 4);
            o0.x += p0.x; o0.y += p0.y; o0.z += p0.z; o0.w += p0.w;
            o1.x += p1.x; o1.y += p1.y; o1.z += p1.z; o1.w += p1.w;
        }
        *(float4*)(po)     = o0;
        *(float4*)(po + 4) = o1;
    }
}

// ================= merged edge pass 1: logits(+exp+sum) & SAGE scatter =================
// no max-subtraction: logits are O(1) by construction, exp is safe.

__global__ void __launch_bounds__(256)
pass1_kernel(const int* __restrict__ em, const float* __restrict__ att,
             const int* __restrict__ ep, const float* __restrict__ ea,
             const float* __restrict__ tWe,
             const int* __restrict__ ei, const float* __restrict__ x_ball)
{
    const int lane = threadIdx.x & 31;
    const int warp = threadIdx.x >> 5;
    const unsigned bx = blockIdx.x;

    if (bx < BG1) {
        // ---- GATv2: logit -> exp -> segment sum ----
        int e0 = (bx * 8 + warp) << 2;
        if (e0 >= EM_N) return;
        int idx = 0;
        if (lane < 8) {
            int e = e0 + (lane & 3);
            if (e < EM_N) idx = em[(lane & 4) ? EM_N + e : e];
        }
        int ss[4], dd[4];
        #pragma unroll
        for (int j = 0; j < 4; j++) {
            ss[j] = __shfl_sync(0xffffffffu, idx, j);
            dd[j] = __shfl_sync(0xffffffffu, idx, 4 + j);
        }
        float4 at = ((const float4*)att)[lane];
        float4 xlv[4], xrv[4];
        #pragma unroll
        for (int j = 0; j < 4; j++) {
            if (e0 + j < EM_N) {
                xlv[j] = ((const float4*)(g_buf + OFF_XL + (size_t)ss[j]*HID))[lane];
                xrv[j] = ((const float4*)(g_buf + OFF_XR + (size_t)dd[j]*HID))[lane];
            }
        }
        #pragma unroll
        for (int j = 0; j < 4; j++) {
            if (e0 + j >= EM_N) break;
            float ex = xlv[j].x + xrv[j].x; ex = ex > 0.f ? ex : 0.2f*ex;
            float ey = xlv[j].y + xrv[j].y; ey = ey > 0.f ? ey : 0.2f*ey;
            float ez = xlv[j].z + xrv[j].z; ez = ez > 0.f ? ez : 0.2f*ez;
            float ew = xlv[j].w + xrv[j].w; ew = ew > 0.f ? ew : 0.2f*ew;
            float p = ex*at.x + ey*at.y + ez*at.z + ew*at.w;
            p += __shfl_xor_sync(0xffffffffu, p, 1);
            p += __shfl_xor_sync(0xffffffffu, p, 2);
            p += __shfl_xor_sync(0xffffffffu, p, 4);
            if ((lane & 7) == 0) {
                int h = lane >> 3;
                float e2 = __expf(p);
                g_buf[OFF_GLOGIT + (size_t)(e0 + j)*NH + h] = e2;
                atomicAdd(&g_buf[OFF_GSUM + (size_t)dd[j]*NH + h], e2);
            }
        }
    } else if (bx < BG1 + BT1) {
        // ---- TransformerConv: logit -> exp -> segment sum ----
        int e0 = ((bx - BG1) * 8 + warp) << 2;
        if (e0 >= EP_N) return;
        int idx = 0;
        if (lane < 8) {
            int e = e0 + (lane & 3);
            if (e < EP_N) idx = ep[(lane & 4) ? EP_N + e : e];
        }
        float eav = 0.f;
        if (lane >= 8 && lane < 12) {
            int e = e0 + (lane & 3);
            if (e < EP_N) eav = ea[e];
        }
        int ss[4], dd[4]; float ev[4];
        #pragma unroll
        for (int j = 0; j < 4; j++) {
            ss[j] = __shfl_sync(0xffffffffu, idx, j);
            dd[j] = __shfl_sync(0xffffffffu, idx, 4 + j);
            ev[j] = __shfl_sync(0xffffffffu, eav, 8 + j);
        }
        float4 we = ((const float4*)tWe)[lane];
        float4 kv[4], qv[4];
        #pragma unroll
        for (int j = 0; j < 4; j++) {
            if (e0 + j < EP_N) {
                kv[j] = ((const float4*)(g_buf + OFF_K + (size_t)ss[j]*HID))[lane];
                qv[j] = ((const float4*)(g_buf + OFF_Q + (size_t)dd[j]*HID))[lane];
            }
        }
        #pragma unroll
        for (int j = 0; j < 4; j++) {
            if (e0 + j >= EP_N) break;
            float e = ev[j];
            float p = qv[j].x*(kv[j].x + e*we.x) + qv[j].y*(kv[j].y + e*we.y)
                    + qv[j].z*(kv[j].z + e*we.z) + qv[j].w*(kv[j].w + e*we.w);
            p += __shfl_xor_sync(0xffffffffu, p, 1);
            p += __shfl_xor_sync(0xffffffffu, p, 2);
            p += __shfl_xor_sync(0xffffffffu, p, 4);
            if ((lane & 7) == 0) {
                int h = lane >> 3;
                float e2 = __expf(p * 0.17677669529663689f);
                g_buf[OFF_TLOGIT + (size_t)(e0 + j)*NH + h] = e2;
                atomicAdd(&g_buf[OFF_TSUM + (size_t)dd[j]*NH + h], e2);
            }
        }
    } else {
        // ---- SAGE scatter (depends only on x_ball) ----
        int e0 = ((bx - BG1 - BT1) * 8 + warp) << 2;
        if (e0 >= EI_N) return;
        int idx = 0;
        if (lane < 8) {
            int e = e0 + (lane & 3);
            if (e < EI_N) idx = ei[(lane & 4) ? EI_N + e : e];
        }
        int ss[4], dd[4];
        #pragma unroll
        for (int j = 0; j < 4; j++) {
            ss[j] = __shfl_sync(0xffffffffu, idx, j);
            dd[j] = __shfl_sync(0xffffffffu, idx, 4 + j);
        }
        float4 xb[4];
        #pragma unroll
        for (int j = 0; j < 4; j++)
            if (e0 + j < EI_N)
                xb[j] = ((const float4*)(x_ball + (size_t)ss[j]*HID))[lane];
        #pragma unroll
        for (int j = 0; j < 4; j++) {
            if (e0 + j >= EI_N) break;
            redAdd4(g_buf + OFF_CTXSUM + (size_t)dd[j]*HID + lane*4,
                    xb[j].x, xb[j].y, xb[j].z, xb[j].w);
            if (lane == 0) atomicAdd(&g_buf[OFF_CNT + dd[j]], 1.0f);
        }
    }
}

// ================= merged edge pass 2: weighted scatters & SAGE mean =================
__global__ void __launch_bounds__(256)
pass2_kernel(const int* __restrict__ em,
             const int* __restrict__ ep, const float* __restrict__ ea,
             const float* __restrict__ tWe)
{
    const int lane = threadIdx.x & 31;
    const int warp = threadIdx.x >> 5;
    const unsigned bx = blockIdx.x;

    if (bx < BG1) {
        // ---- GAT scatter into ACC ----
        int e0 = (bx * 8 + warp) << 2;
        if (e0 >= EM_N) return;
        int idx = 0;
        if (lane < 8) {
            int e = e0 + (lane & 3);
            if (e < EM_N) idx = em[(lane & 4) ? EM_N + e : e];
        }
        int ss[4], dd[4];
        #pragma unroll
        for (int j = 0; j < 4; j++) {
            ss[j] = __shfl_sync(0xffffffffu, idx, j);
            dd[j] = __shfl_sync(0xffffffffu, idx, 4 + j);
        }
        int h = lane >> 3;
        float lg[4], sm[4]; float4 xl[4];
        #pragma unroll
        for (int j = 0; j < 4; j++) {
            if (e0 + j < EM_N) {
                lg[j] = g_buf[OFF_GLOGIT + (size_t)(e0 + j)*NH + h];
                sm[j] = g_buf[OFF_GSUM + (size_t)dd[j]*NH + h];
                xl[j] = ((const float4*)(g_buf + OFF_XL + (size_t)ss[j]*HID))[lane];
            }
        }
        #pragma unroll
        for (int j = 0; j < 4; j++) {
            if (e0 + j >= EM_N) break;
            float alpha = lg[j] / (sm[j] + 1e-16f);
            redAdd4(g_buf + OFF_ACC + (size_t)dd[j]*HID + lane*4,
                    xl[j].x*alpha, xl[j].y*alpha, xl[j].z*alpha, xl[j].w*alpha);
        }
    } else if (bx < BG1 + BT1) {
        // ---- TR scatter into ACC ----
        int e0 = ((bx - BG1) * 8 + warp) << 2;
        if (e0 >= EP_N) return;
        int idx = 0;
        if (lane < 8) {
            int e = e0 + (lane & 3);
            if (e < EP_N) idx = ep[(lane & 4) ? EP_N + e : e];
        }
        float eav = 0.f;
        if (lane >= 8 && lane < 12) {
            int e = e0 + (lane & 3);
            if (e < EP_N) eav = ea[e];
        }
        int ss[4], dd[4]; float ev[4];
        #pragma unroll
        for (int j = 0; j < 4; j++) {
            ss[j] = __shfl_sync(0xffffffffu, idx, j);
            dd[j] = __shfl_sync(0xffffffffu, idx, 4 + j);
            ev[j] = __shfl_sync(0xffffffffu, eav, 8 + j);
        }
        int h = lane >> 3;
        float4 we = ((const float4*)tWe)[lane];
        float lg[4], sm[4]; float4 vv[4];
        #pragma unroll
        for (int j = 0; j < 4; j++) {
            if (e0 + j < EP_N) {
                lg[j] = g_buf[OFF_TLOGIT + (size_t)(e0 + j)*NH + h];
                sm[j] = g_buf[OFF_TSUM + (size_t)dd[j]*NH + h];
                vv[j] = ((const float4*)(g_buf + OFF_V + (size_t)ss[j]*HID))[lane];
            }
        }
        #pragma unroll
        for (int j = 0; j < 4; j++) {
            if (e0 + j >= EP_N) break;
            float alpha = lg[j] / (sm[j] + 1e-16f);
            float e = ev[j];
            redAdd4(g_buf + OFF_ACC + (size_t)dd[j]*HID + lane*4,
                    (vv[j].x + e*we.x)*alpha, (vv[j].y + e*we.y)*alpha,
                    (vv[j].z + e*we.z)*alpha, (vv[j].w + e*we.w)*alpha);
        }
    } else {
        // ---- SAGE mean ----
        int i = (bx - BG1 - BT1) * 256 + threadIdx.x;
        if (i < NC*HID) {
            int c = i >> 7;
            g_buf[OFF_MEAN + i] = g_buf[OFF_CTXSUM + i] / fmaxf(g_buf[OFF_CNT + c], 1.0f);
        }
    }
}

// ---------------- LayerNorm: out = LN(A + B [+ bcast]) ----------------
__global__ void ln_kernel(const float* __restrict__ A, const float* __restrict__ B,
                          const float* __restrict__ bcast, const float* __restrict__ g,
                          const float* __restrict__ b, float* __restrict__ out, int n) {
    int r = (blockIdx.x << 3) + (threadIdx.x >> 5);
    if (r >= n) return;
    int lane = threadIdx.x & 31;
    float4 p = ((const float4*)(A + (size_t)r*HID))[lane];
    float4 q = ((const float4*)(B + (size_t)r*HID))[lane];
    p.x += q.x; p.y += q.y; p.z += q.z; p.w += q.w;
    if (bcast) {
        float4 c4 = ((const float4*)bcast)[lane];
        p.x += c4.x; p.y += c4.y; p.z += c4.z; p.w += c4.w;
    }
    float s = p.x + p.y + p.z + p.w;
    float sq = p.x*p.x + p.y*p.y + p.z*p.z + p.w*p.w;
    #pragma unroll
    for (int off = 16; off >= 1; off >>= 1) {
        s  += __shfl_xor_sync(0xffffffffu, s, off);
        sq += __shfl_xor_sync(0xffffffffu, sq, off);
    }
    float mu = s * (1.0f/HID);
    float var = sq * (1.0f/HID) - mu*mu;
    float rstd = rsqrtf(var + 1e-5f);
    float4 gg = ((const float4*)g)[lane];
    float4 bb = ((const float4*)b)[lane];
    float4 o;
    o.x = (p.x - mu)*rstd*gg.x + bb.x;
    o.y = (p.y - mu)*rstd*gg.y + bb.y;
    o.z = (p.z - mu)*rstd*gg.z + bb.z;
    o.w = (p.w - mu)*rstd*gg.w + bb.w;
    ((float4*)(out + (size_t)r*HID))[lane] = o;
}

// ---------------- launch ----------------
extern "C" void kernel_launch(void* const* d_in, const int* in_sizes, int n_in,
                              void* d_out, int out_size)
{
    const float* x_ball    = (const float*)d_in[0];
    const float* x_player  = (const float*)d_in[1];
    const float* x_context = (const float*)d_in[2];
    const int*   em   = (const int*)d_in[3];
    const int*   ep   = (const int*)d_in[4];
    const int*   ei   = (const int*)d_in[5];
    const float* ea_p = (const float*)d_in[6];
    const float* gWl  = (const float*)d_in[7];
    const float* gWr  = (const float*)d_in[8];
    const float* gatt = (const float*)d_in[9];
    const float* gb   = (const float*)d_in[10];
    const float* tWq  = (const float*)d_in[11];
    const float* tbq  = (const float*)d_in[12];
    const float* tWk  = (const float*)d_in[13];
    const float* tbk  = (const float*)d_in[14];
    const float* tWv  = (const float*)d_in[15];
    const float* tbv  = (const float*)d_in[16];
    const float* tWe  = (const float*)d_in[17];
    const float* tWs  = (const float*)d_in[18];
    const float* tbs  = (const float*)d_in[19];
    const float* sWl  = (const float*)d_in[20];
    const float* sbl  = (const float*)d_in[21];
    const float* sWr  = (const float*)d_in[22];
    const float* lbg  = (const float*)d_in[23];
    const float* lbb  = (const float*)d_in[24];
    const float* lcg  = (const float*)d_in[25];
    const float* lcb  = (const float*)d_in[26];
    float* out = (float*)d_out;

    float* base = nullptr;
    cudaGetSymbolAddress((void**)&base, g_buf);
    float* s_xl   = base + OFF_XL;
    float* s_xr   = base + OFF_XR;
    float* s_q    = base + OFF_Q;
    float* s_k    = base + OFF_K;
    float* s_v    = base + OFF_V;
    float* s_acc  = base + OFF_ACC;
    float* s_mean = base + OFF_MEAN;
    float* s_sage = base + OFF_SAGE;

    const int T = 256;

    cudaFuncSetAttribute(gemm128_v2, cudaFuncAttributeMaxDynamicSharedMemorySize, GEMM_SMEM);
    cudaFuncSetAttribute(big5_mma, cudaFuncAttributeMaxDynamicSharedMemorySize, SMEM_BIG5);

    // init sum/count buffers
    init_kernel<<<(NC*HID + T-1)/T, T>>>();

    // fused HMMA GEMM: q,k,v,(skip->acc),xr
    big5_mma<<<NTILE, 256, SMEM_BIG5>>>(x_ball, tWq, tWk, tWv, tWs, gWr,
                                        s_q, s_k, s_v, s_acc, s_xr,
                                        tbq, tbk, tbv, tbs);

    // small transforms on the SIMT path
    dim3 gNP((NP + 127)/128, 2), gNC((NC + 127)/128, 2);
    gemm128_v2<<<gNP, 128, GEMM_SMEM>>>(x_player, gWl, nullptr, s_xl, NP, 0);

    // merged pass 1: logits+exp+sum (GAT, TR) and SAGE scatter
    pass1_kernel<<<PASS1_GRID, T>>>(em, gatt, ep, ea_p, tWe, ei, x_ball);

    // merged pass 2: weighted scatters (GAT, TR) and SAGE mean
    pass2_kernel<<<PASS2_GRID, T>>>(em, ep, ea_p, tWe);

    // SAGE gemms
    gemm128_v2<<<gNC, 128, GEMM_SMEM>>>(x_context, sWr, nullptr, s_sage, NC, 0);
    gemm128_v2<<<gNC, 128, GEMM_SMEM>>>(s_mean,    sWl, sbl,     s_sage, NC, 1);

    // outputs: ball = LN(acc + x_ball + g_b), ctx = LN(sage + x_ctx), player passthrough
    ln_kernel<<<(NB + 7)/8, T>>>(s_acc, x_ball, gb, lbg, lbb, out, NB);
    ln_kernel<<<(NC + 7)/8, T>>>(s_sage, x_context, nullptr, lcg, lcb, out + (size_t)NB*HID, NC);
    cudaMemcpyAsync(out + (size_t)(NB+NC)*HID, x_player, (size_t)NP*HID*sizeof(float),
                    cudaMemcpyDeviceToDevice);
}

// round 9
// speedup vs baseline: 4.7235x; 1.6832x over previous
#include <cuda_runtime.h>
#include <cuda_bf16.h>
#include <cstdint>

#define HID 128
#define NH 4
#define NB 60000
#define NP 2000
#define NC 4000
#define EM_N 150000
#define EP_N 300000
#define EI_N 150000
#define NTILE 469          // ceil(NB/128)
#define PTILE 16           // ceil(NP/128)
#define CTILE 32           // ceil(NC/128)

// block counts for merged edge passes (4 edges/warp, 8 warps/block => 32 edges/block)
#define BG1 ((EM_N/4 + 7)/8)
#define BT1 ((EP_N/4 + 7)/8)
#define BS1 ((EI_N/4 + 7)/8)
#define PASS1_GRID (BG1 + BT1 + BS1)
#define MEAN_BLKS ((NC*HID + 255)/256)
#define PASS2_GRID (BG1 + BT1 + MEAN_BLKS)

// ---- scratch layout (floats) ----
#define SZ_NBH (NB*HID)
#define OFF_XL     0
#define OFF_XR     (OFF_XL + NP*HID)
#define OFF_Q      (OFF_XR + SZ_NBH)
#define OFF_K      (OFF_Q + SZ_NBH)
#define OFF_V      (OFF_K + SZ_NBH)
#define OFF_ACC    (OFF_V + SZ_NBH)
#define OFF_CTXSUM (OFF_ACC + SZ_NBH)
#define OFF_MEAN   (OFF_CTXSUM + NC*HID)
#define OFF_SAGE   (OFF_MEAN + NC*HID)
#define OFF_CNT    (OFF_SAGE + NC*HID)
#define OFF_GLOGIT (OFF_CNT + NC)
#define OFF_TLOGIT (OFF_GLOGIT + EM_N*NH)
#define OFF_GSUM   (OFF_TLOGIT + EP_N*NH)
#define OFF_TSUM   (OFF_GSUM + NB*NH)
#define TOTAL_SCRATCH (OFF_TSUM + NB*NH)

__device__ __align__(256) float g_buf[TOTAL_SCRATCH];

// pre-converted weights: 8 matrices x {hi,lo} in ldmatrix-ready layout (k*STR + n)
#define STR 136
#define WP_ELEMS (128*STR)          // 17408 bf16 = 34816 B
__device__ __align__(1024) __nv_bfloat16 g_Wprep[8*2*WP_ELEMS];

// ---------------- PTX helpers ----------------
__device__ __forceinline__ uint32_t smem_u32(const void* p) {
    uint32_t a;
    asm("{ .reg .u64 t; cvta.to.shared.u64 t, %1; cvt.u32.u64 %0, t; }" : "=r"(a) : "l"(p));
    return a;
}
__device__ __forceinline__ void ldsm4(uint32_t& r0, uint32_t& r1, uint32_t& r2, uint32_t& r3,
                                      uint32_t addr) {
    asm volatile("ldmatrix.sync.aligned.m8n8.x4.shared.b16 {%0,%1,%2,%3}, [%4];"
                 : "=r"(r0), "=r"(r1), "=r"(r2), "=r"(r3) : "r"(addr));
}
__device__ __forceinline__ void ldsm4t(uint32_t& r0, uint32_t& r1, uint32_t& r2, uint32_t& r3,
                                       uint32_t addr) {
    asm volatile("ldmatrix.sync.aligned.m8n8.x4.trans.shared.b16 {%0,%1,%2,%3}, [%4];"
                 : "=r"(r0), "=r"(r1), "=r"(r2), "=r"(r3) : "r"(addr));
}
__device__ __forceinline__ void mma16816(float* C, const uint32_t* A, uint32_t B0, uint32_t B1) {
    asm volatile("mma.sync.aligned.m16n8k16.row.col.f32.bf16.bf16.f32 "
                 "{%0,%1,%2,%3}, {%4,%5,%6,%7}, {%8,%9}, {%0,%1,%2,%3};"
                 : "+f"(C[0]), "+f"(C[1]), "+f"(C[2]), "+f"(C[3])
                 : "r"(A[0]), "r"(A[1]), "r"(A[2]), "r"(A[3]), "r"(B0), "r"(B1));
}
#define CP_ASYNC16(sm, gm) \
    asm volatile("cp.async.ca.shared.global [%0], [%1], 16;" :: "r"(sm), "l"(gm))
#define CP_COMMIT() asm volatile("cp.async.commit_group;" ::: "memory")
#define CP_WAIT1() asm volatile("cp.async.wait_group 1;" ::: "memory")
#define CP_WAIT0() asm volatile("cp.async.wait_group 0;" ::: "memory")

// ---------------- weight prep: fp32 -> hi/lo bf16, ldsm layout ----------------
__global__ void prepW_kernel(const float* __restrict__ w0, const float* __restrict__ w1,
                             const float* __restrict__ w2, const float* __restrict__ w3,
                             const float* __restrict__ w4, const float* __restrict__ w5,
                             const float* __restrict__ w6, const float* __restrict__ w7)
{
    int idx = blockIdx.x * blockDim.x + threadIdx.x;
    if (idx >= 8 * 16384) return;
    int m = idx >> 14, rem = idx & 16383;
    int k = rem >> 7, n = rem & 127;
    const float* W = (m == 0) ? w0 : (m == 1) ? w1 : (m == 2) ? w2 : (m == 3) ? w3
                   : (m == 4) ? w4 : (m == 5) ? w5 : (m == 6) ? w6 : w7;
    float v = W[(size_t)k * HID + n];
    __nv_bfloat16 hi = __float2bfloat16(v);
    __nv_bfloat16 lo = __float2bfloat16(v - __bfloat162float(hi));
    g_Wprep[(size_t)(m*2 + 0)*WP_ELEMS + k*STR + n] = hi;
    g_Wprep[(size_t)(m*2 + 1)*WP_ELEMS + k*STR + n] = lo;
}

// ---------------- big HMMA GEMM: x_ball x {q,k,v,skip,xr}, x_player x {gWl} ----------------
#define SMA_H 0
#define SMA_L 34816
#define SMW0  69632
#define SMW1  139264
#define SMEM_BIG5 208896

__device__ __forceinline__ void stageW_async(uint32_t smW, int widx, int tid) {
    const char* gh = (const char*)g_Wprep + (size_t)(widx*2)*WP_ELEMS*2;
    const char* gl = gh + WP_ELEMS*2;
    for (int j = tid; j < 2176; j += 256) {
        CP_ASYNC16(smW + j*16, gh + j*16);
        CP_ASYNC16(smW + 34816 + j*16, gl + j*16);
    }
}

__global__ void __launch_bounds__(256)
big5_mma(const float* __restrict__ xball, const float* __restrict__ xplayer,
         float* __restrict__ o0, float* __restrict__ o1, float* __restrict__ o2,
         float* __restrict__ o3, float* __restrict__ o4, float* __restrict__ o5,
         const float* __restrict__ b0, const float* __restrict__ b1,
         const float* __restrict__ b2, const float* __restrict__ b3)
{
    extern __shared__ char smem[];
    const uint32_t sb = smem_u32(smem);
    const int tid = threadIdx.x, lane = tid & 31, warp = tid >> 5;
    const int wm = warp >> 1, wn = warp & 1;
    const bool player = (blockIdx.x >= NTILE);
    const int tile = player ? (blockIdx.x - NTILE) : blockIdx.x;
    const int rbase = tile * 128;
    const int nrows = player ? NP : NB;
    const float* Asrc = player ? xplayer : xball;
    const int nw = player ? 1 : 5;

    // stage A tile as hi/lo bf16
    for (int idx = tid; idx < 8192; idx += 256) {
        int row = idx >> 6, kp = idx & 63;
        int grow = rbase + row;
        float2 v = make_float2(0.f, 0.f);
        if (grow < nrows) v = ((const float2*)(Asrc + (size_t)grow * HID))[kp];
        __nv_bfloat162 h2 = __float22bfloat162_rn(v);
        float2 lo = make_float2(v.x - __bfloat162float(h2.x),
                                v.y - __bfloat162float(h2.y));
        __nv_bfloat162 l2 = __float22bfloat162_rn(lo);
        uint32_t off = (uint32_t)(row * STR + kp * 2) * 2;
        *(uint32_t*)(smem + SMA_H + off) = *(uint32_t*)&h2;
        *(uint32_t*)(smem + SMA_L + off) = *(uint32_t*)&l2;
    }

    // prefetch W[0]
    stageW_async(sb + SMW0, player ? 5 : 0, tid);
    CP_COMMIT();

    float*       outs[5]   = {o0, o1, o2, o3, o4};
    const float* biases[5] = {b0, b1, b2, b3, nullptr};

    const int gid = lane >> 2, tig = lane & 3;
    const int sub = lane >> 3, lr = lane & 7;
    const int f_r = ((sub & 1) << 3) + lr;
    const int f_c = (sub >> 1) << 3;

    for (int i = 0; i < nw; i++) {
        if (i + 1 < nw) {
            stageW_async(sb + (((i+1) & 1) ? SMW1 : SMW0), i + 1, tid);
            CP_COMMIT();
            CP_WAIT1();
        } else {
            CP_WAIT0();
        }
        __syncthreads();

        const uint32_t wbase = sb + ((i & 1) ? SMW1 : SMW0);

        float acc[2][8][4];
        #pragma unroll
        for (int mt = 0; mt < 2; mt++)
            #pragma unroll
            for (int j = 0; j < 8; j++)
                #pragma unroll
                for (int c = 0; c < 4; c++) acc[mt][j][c] = 0.f;

        #pragma unroll
        for (int ks = 0; ks < 8; ks++) {
            const int K0 = ks * 16;
            uint32_t ah[2][4], al[2][4];
            #pragma unroll
            for (int mt = 0; mt < 2; mt++) {
                uint32_t ad = sb + SMA_H +
                    (uint32_t)((wm*32 + mt*16 + f_r) * STR + K0 + f_c) * 2;
                ldsm4(ah[mt][0], ah[mt][1], ah[mt][2], ah[mt][3], ad);
                ldsm4(al[mt][0], al[mt][1], al[mt][2], al[mt][3], ad + (SMA_L - SMA_H));
            }
            uint32_t bh[4][4], bl[4][4];
            #pragma unroll
            for (int nt = 0; nt < 4; nt++) {
                uint32_t wd = wbase +
                    (uint32_t)((K0 + f_r) * STR + wn*64 + nt*16 + f_c) * 2;
                ldsm4t(bh[nt][0], bh[nt][1], bh[nt][2], bh[nt][3], wd);
                ldsm4t(bl[nt][0], bl[nt][1], bl[nt][2], bl[nt][3], wd + 34816);
            }
            #pragma unroll
            for (int mt = 0; mt < 2; mt++)
                #pragma unroll
                for (int nt = 0; nt < 4; nt++)
                    #pragma unroll
                    for (int h = 0; h < 2; h++) {
                        float* C = acc[mt][nt*2 + h];
                        mma16816(C, ah[mt], bh[nt][2*h], bh[nt][2*h+1]);
                        mma16816(C, ah[mt], bl[nt][2*h], bl[nt][2*h+1]);
                        mma16816(C, al[mt], bh[nt][2*h], bh[nt][2*h+1]);
                    }
        }

        const float* bias = player ? nullptr : biases[i];
        float* outp = player ? o5 : outs[i];
        #pragma unroll
        for (int mt = 0; mt < 2; mt++) {
            int r0g = rbase + wm*32 + mt*16 + gid;
            #pragma unroll
            for (int j = 0; j < 8; j++) {
                int cn = wn*64 + j*8 + tig*2;
                float bx = bias ? bias[cn]   : 0.f;
                float by = bias ? bias[cn+1] : 0.f;
                if (r0g < nrows)
                    *(float2*)(outp + (size_t)r0g*HID + cn) =
                        make_float2(acc[mt][j][0] + bx, acc[mt][j][1] + by);
                if (r0g + 8 < nrows)
                    *(float2*)(outp + (size_t)(r0g+8)*HID + cn) =
                        make_float2(acc[mt][j][2] + bx, acc[mt][j][3] + by);
            }
        }
        __syncthreads();
    }
}

// ---------------- sage HMMA: s_sage = x_ctx@sWr + mean@sWl + sbl ----------------
#define SMEM_SAGE 139264

__global__ void __launch_bounds__(256)
sage_mma(const float* __restrict__ xctx, const float* __restrict__ mean,
         float* __restrict__ outp, const float* __restrict__ sbl)
{
    extern __shared__ char smem[];
    const uint32_t sb = smem_u32(smem);
    const int tid = threadIdx.x, lane = tid & 31, warp = tid >> 5;
    const int wm = warp >> 1, wn = warp & 1;
    const int rbase = blockIdx.x * 128;

    const int gid = lane >> 2, tig = lane & 3;
    const int sub = lane >> 3, lr = lane & 7;
    const int f_r = ((sub & 1) << 3) + lr;
    const int f_c = (sub >> 1) << 3;

    float acc[2][8][4];
    #pragma unroll
    for (int mt = 0; mt < 2; mt++)
        #pragma unroll
        for (int j = 0; j < 8; j++)
            #pragma unroll
            for (int c = 0; c < 4; c++) acc[mt][j][c] = 0.f;

    for (int it = 0; it < 2; it++) {
        const float* Asrc = it ? mean : xctx;
        const int widx = 6 + it;
        // stage A
        for (int idx = tid; idx < 8192; idx += 256) {
            int row = idx >> 6, kp = idx & 63;
            int grow = rbase + row;
            float2 v = make_float2(0.f, 0.f);
            if (grow < NC) v = ((const float2*)(Asrc + (size_t)grow * HID))[kp];
            __nv_bfloat162 h2 = __float22bfloat162_rn(v);
            float2 lo = make_float2(v.x - __bfloat162float(h2.x),
                                    v.y - __bfloat162float(h2.y));
            __nv_bfloat162 l2 = __float22bfloat162_rn(lo);
            uint32_t off = (uint32_t)(row * STR + kp * 2) * 2;
            *(uint32_t*)(smem + SMA_H + off) = *(uint32_t*)&h2;
            *(uint32_t*)(smem + SMA_L + off) = *(uint32_t*)&l2;
        }
        // stage W (plain copy of prepped bf16)
        {
            const uint4* gh = (const uint4*)((const char*)g_Wprep + (size_t)(widx*2)*WP_ELEMS*2);
            const uint4* gl = (const uint4*)((const char*)g_Wprep + (size_t)(widx*2+1)*WP_ELEMS*2);
            uint4* dh = (uint4*)(smem + SMW0);
            uint4* dl = (uint4*)(smem + SMW0 + 34816);
            for (int j = tid; j < 2176; j += 256) { dh[j] = gh[j]; dl[j] = gl[j]; }
        }
        __syncthreads();

        #pragma unroll
        for (int ks = 0; ks < 8; ks++) {
            const int K0 = ks * 16;
            uint32_t ah[2][4], al[2][4];
            #pragma unroll
            for (int mt = 0; mt < 2; mt++) {
                uint32_t ad = sb + SMA_H +
                    (uint32_t)((wm*32 + mt*16 + f_r) * STR + K0 + f_c) * 2;
                ldsm4(ah[mt][0], ah[mt][1], ah[mt][2], ah[mt][3], ad);
                ldsm4(al[mt][0], al[mt][1], al[mt][2], al[mt][3], ad + (SMA_L - SMA_H));
            }
            uint32_t bh[4][4], bl[4][4];
            #pragma unroll
            for (int nt = 0; nt < 4; nt++) {
                uint32_t wd = sb + SMW0 +
                    (uint32_t)((K0 + f_r) * STR + wn*64 + nt*16 + f_c) * 2;
                ldsm4t(bh[nt][0], bh[nt][1], bh[nt][2], bh[nt][3], wd);
                ldsm4t(bl[nt][0], bl[nt][1], bl[nt][2], bl[nt][3], wd + 34816);
            }
            #pragma unroll
            for (int mt = 0; mt < 2; mt++)
                #pragma unroll
                for (int nt = 0; nt < 4; nt++)
                    #pragma unroll
                    for (int h = 0; h < 2; h++) {
                        float* C = acc[mt][nt*2 + h];
                        mma16816(C, ah[mt], bh[nt][2*h], bh[nt][2*h+1]);
                        mma16816(C, ah[mt], bl[nt][2*h], bl[nt][2*h+1]);
                        mma16816(C, al[mt], bh[nt][2*h], bh[nt][2*h+1]);
                    }
        }
        __syncthreads();
    }

    #pragma unroll
    for (int mt = 0; mt < 2; mt++) {
        int r0g = rbase + wm*32 + mt*16 + gid;
        #pragma unroll
        for (int j = 0; j < 8; j++) {
            int cn = wn*64 + j*8 + tig*2;
            float bx = sbl[cn], by = sbl[cn+1];
            if (r0g < NC)
                *(float2*)(outp + (size_t)r0g*HID + cn) =
                    make_float2(acc[mt][j][0] + bx, acc[mt][j][1] + by);
            if (r0g + 8 < NC)
                *(float2*)(outp + (size_t)(r0g+8)*HID + cn) =
                    make_float2(acc[mt][j][2] + bx, acc[mt][j][3] + by);
        }
    }
}

// ---------------- helpers ----------------
__device__ __forceinline__ void redAdd4(float* p, float a, float b, float c, float d) {
    asm volatile("red.global.add.v4.f32 [%0], {%1,%2,%3,%4};"
                 :: "l"(p), "f"(a), "f"(b), "f"(c), "f"(d) : "memory");
}

// ---------------- init ----------------
__global__ void init_kernel() {
    int i = blockIdx.x * blockDim.x + threadIdx.x;
    if (i < NB*NH) {
        g_buf[OFF_GSUM + i] = 0.f;
        g_buf[OFF_TSUM + i] = 0.f;
    }
    if (i < NC*HID) g_buf[OFF_CTXSUM + i] = 0.f;
    if (i < NC) g_buf[OFF_CNT + i] = 0.f;
}

// ================= merged edge pass 1 =================
__global__ void __launch_bounds__(256)
pass1_kernel(const int* __restrict__ em, const float* __restrict__ att,
             const int* __restrict__ ep, const float* __restrict__ ea,
             const float* __restrict__ tWe,
             const int* __restrict__ ei, const float* __restrict__ x_ball)
{
    const int lane = threadIdx.x & 31;
    const int warp = threadIdx.x >> 5;
    const unsigned bx = blockIdx.x;

    if (bx < BG1) {
        int e0 = (bx * 8 + warp) << 2;
        if (e0 >= EM_N) return;
        int idx = 0;
        if (lane < 8) {
            int e = e0 + (lane & 3);
            if (e < EM_N) idx = em[(lane & 4) ? EM_N + e : e];
        }
        int ss[4], dd[4];
        #pragma unroll
        for (int j = 0; j < 4; j++) {
            ss[j] = __shfl_sync(0xffffffffu, idx, j);
            dd[j] = __shfl_sync(0xffffffffu, idx, 4 + j);
        }
        float4 at = ((const float4*)att)[lane];
        float4 xlv[4], xrv[4];
        #pragma unroll
        for (int j = 0; j < 4; j++) {
            if (e0 + j < EM_N) {
                xlv[j] = ((const float4*)(g_buf + OFF_XL + (size_t)ss[j]*HID))[lane];
                xrv[j] = ((const float4*)(g_buf + OFF_XR + (size_t)dd[j]*HID))[lane];
            }
        }
        #pragma unroll
        for (int j = 0; j < 4; j++) {
            if (e0 + j >= EM_N) break;
            float ex = xlv[j].x + xrv[j].x; ex = ex > 0.f ? ex : 0.2f*ex;
            float ey = xlv[j].y + xrv[j].y; ey = ey > 0.f ? ey : 0.2f*ey;
            float ez = xlv[j].z + xrv[j].z; ez = ez > 0.f ? ez : 0.2f*ez;
            float ew = xlv[j].w + xrv[j].w; ew = ew > 0.f ? ew : 0.2f*ew;
            float p = ex*at.x + ey*at.y + ez*at.z + ew*at.w;
            p += __shfl_xor_sync(0xffffffffu, p, 1);
            p += __shfl_xor_sync(0xffffffffu, p, 2);
            p += __shfl_xor_sync(0xffffffffu, p, 4);
            if ((lane & 7) == 0) {
                int h = lane >> 3;
                float e2 = __expf(p);
                g_buf[OFF_GLOGIT + (size_t)(e0 + j)*NH + h] = e2;
                atomicAdd(&g_buf[OFF_GSUM + (size_t)dd[j]*NH + h], e2);
            }
        }
    } else if (bx < BG1 + BT1) {
        int e0 = ((bx - BG1) * 8 + warp) << 2;
        if (e0 >= EP_N) return;
        int idx = 0;
        if (lane < 8) {
            int e = e0 + (lane & 3);
            if (e < EP_N) idx = ep[(lane & 4) ? EP_N + e : e];
        }
        float eav = 0.f;
        if (lane >= 8 && lane < 12) {
            int e = e0 + (lane & 3);
            if (e < EP_N) eav = ea[e];
        }
        int ss[4], dd[4]; float ev[4];
        #pragma unroll
        for (int j = 0; j < 4; j++) {
            ss[j] = __shfl_sync(0xffffffffu, idx, j);
            dd[j] = __shfl_sync(0xffffffffu, idx, 4 + j);
            ev[j] = __shfl_sync(0xffffffffu, eav, 8 + j);
        }
        float4 we = ((const float4*)tWe)[lane];
        float4 kv[4], qv[4];
        #pragma unroll
        for (int j = 0; j < 4; j++) {
            if (e0 + j < EP_N) {
                kv[j] = ((const float4*)(g_buf + OFF_K + (size_t)ss[j]*HID))[lane];
                qv[j] = ((const float4*)(g_buf + OFF_Q + (size_t)dd[j]*HID))[lane];
            }
        }
        #pragma unroll
        for (int j = 0; j < 4; j++) {
            if (e0 + j >= EP_N) break;
            float e = ev[j];
            float p = qv[j].x*(kv[j].x + e*we.x) + qv[j].y*(kv[j].y + e*we.y)
                    + qv[j].z*(kv[j].z + e*we.z) + qv[j].w*(kv[j].w + e*we.w);
            p += __shfl_xor_sync(0xffffffffu, p, 1);
            p += __shfl_xor_sync(0xffffffffu, p, 2);
            p += __shfl_xor_sync(0xffffffffu, p, 4);
            if ((lane & 7) == 0) {
                int h = lane >> 3;
                float e2 = __expf(p * 0.17677669529663689f);
                g_buf[OFF_TLOGIT + (size_t)(e0 + j)*NH + h] = e2;
                atomicAdd(&g_buf[OFF_TSUM + (size_t)dd[j]*NH + h], e2);
            }
        }
    } else {
        int e0 = ((bx - BG1 - BT1) * 8 + warp) << 2;
        if (e0 >= EI_N) return;
        int idx = 0;
        if (lane < 8) {
            int e = e0 + (lane & 3);
            if (e < EI_N) idx = ei[(lane & 4) ? EI_N + e : e];
        }
        int ss[4], dd[4];
        #pragma unroll
        for (int j = 0; j < 4; j++) {
            ss[j] = __shfl_sync(0xffffffffu, idx, j);
            dd[j] = __shfl_sync(0xffffffffu, idx, 4 + j);
        }
        float4 xb[4];
        #pragma unroll
        for (int j = 0; j < 4; j++)
            if (e0 + j < EI_N)
                xb[j] = ((const float4*)(x_ball + (size_t)ss[j]*HID))[lane];
        #pragma unroll
        for (int j = 0; j < 4; j++) {
            if (e0 + j >= EI_N) break;
            redAdd4(g_buf + OFF_CTXSUM + (size_t)dd[j]*HID + lane*4,
                    xb[j].x, xb[j].y, xb[j].z, xb[j].w);
            if (lane == 0) atomicAdd(&g_buf[OFF_CNT + dd[j]], 1.0f);
        }
    }
}

// ================= merged edge pass 2 =================
__global__ void __launch_bounds__(256)
pass2_kernel(const int* __restrict__ em,
             const int* __restrict__ ep, const float* __restrict__ ea,
             const float* __restrict__ tWe)
{
    const int lane = threadIdx.x & 31;
    const int warp = threadIdx.x >> 5;
    const unsigned bx = blockIdx.x;

    if (bx < BG1) {
        int e0 = (bx * 8 + warp) << 2;
        if (e0 >= EM_N) return;
        int idx = 0;
        if (lane < 8) {
            int e = e0 + (lane & 3);
            if (e < EM_N) idx = em[(lane & 4) ? EM_N + e : e];
        }
        int ss[4], dd[4];
        #pragma unroll
        for (int j = 0; j < 4; j++) {
            ss[j] = __shfl_sync(0xffffffffu, idx, j);
            dd[j] = __shfl_sync(0xffffffffu, idx, 4 + j);
        }
        int h = lane >> 3;
        float lg[4], sm[4]; float4 xl[4];
        #pragma unroll
        for (int j = 0; j < 4; j++) {
            if (e0 + j < EM_N) {
                lg[j] = g_buf[OFF_GLOGIT + (size_t)(e0 + j)*NH + h];
                sm[j] = g_buf[OFF_GSUM + (size_t)dd[j]*NH + h];
                xl[j] = ((const float4*)(g_buf + OFF_XL + (size_t)ss[j]*HID))[lane];
            }
        }
        #pragma unroll
        for (int j = 0; j < 4; j++) {
            if (e0 + j >= EM_N) break;
            float alpha = lg[j] / (sm[j] + 1e-16f);
            redAdd4(g_buf + OFF_ACC + (size_t)dd[j]*HID + lane*4,
                    xl[j].x*alpha, xl[j].y*alpha, xl[j].z*alpha, xl[j].w*alpha);
        }
    } else if (bx < BG1 + BT1) {
        int e0 = ((bx - BG1) * 8 + warp) << 2;
        if (e0 >= EP_N) return;
        int idx = 0;
        if (lane < 8) {
            int e = e0 + (lane & 3);
            if (e < EP_N) idx = ep[(lane & 4) ? EP_N + e : e];
        }
        float eav = 0.f;
        if (lane >= 8 && lane < 12) {
            int e = e0 + (lane & 3);
            if (e < EP_N) eav = ea[e];
        }
        int ss[4], dd[4]; float ev[4];
        #pragma unroll
        for (int j = 0; j < 4; j++) {
            ss[j] = __shfl_sync(0xffffffffu, idx, j);
            dd[j] = __shfl_sync(0xffffffffu, idx, 4 + j);
            ev[j] = __shfl_sync(0xffffffffu, eav, 8 + j);
        }
        int h = lane >> 3;
        float4 we = ((const float4*)tWe)[lane];
        float lg[4], sm[4]; float4 vv[4];
        #pragma unroll
        for (int j = 0; j < 4; j++) {
            if (e0 + j < EP_N) {
                lg[j] = g_buf[OFF_TLOGIT + (size_t)(e0 + j)*NH + h];
                sm[j] = g_buf[OFF_TSUM + (size_t)dd[j]*NH + h];
                vv[j] = ((const float4*)(g_buf + OFF_V + (size_t)ss[j]*HID))[lane];
            }
        }
        #pragma unroll
        for (int j = 0; j < 4; j++) {
            if (e0 + j >= EP_N) break;
            float alpha = lg[j] / (sm[j] + 1e-16f);
            float e = ev[j];
            redAdd4(g_buf + OFF_ACC + (size_t)dd[j]*HID + lane*4,
                    (vv[j].x + e*we.x)*alpha, (vv[j].y + e*we.y)*alpha,
                    (vv[j].z + e*we.z)*alpha, (vv[j].w + e*we.w)*alpha);
        }
    } else {
        int i = (bx - BG1 - BT1) * 256 + threadIdx.x;
        if (i < NC*HID) {
            int c = i >> 7;
            g_buf[OFF_MEAN + i] = g_buf[OFF_CTXSUM + i] / fmaxf(g_buf[OFF_CNT + c], 1.0f);
        }
    }
}

// ---------------- LayerNorm: out = LN(A + B [+ bcast]) ----------------
__global__ void ln_kernel(const float* __restrict__ A, const float* __restrict__ B,
                          const float* __restrict__ bcast, const float* __restrict__ g,
                          const float* __restrict__ b, float* __restrict__ out, int n) {
    int r = (blockIdx.x << 3) + (threadIdx.x >> 5);
    if (r >= n) return;
    int lane = threadIdx.x & 31;
    float4 p = ((const float4*)(A + (size_t)r*HID))[lane];
    float4 q = ((const float4*)(B + (size_t)r*HID))[lane];
    p.x += q.x; p.y += q.y; p.z += q.z; p.w += q.w;
    if (bcast) {
        float4 c4 = ((const float4*)bcast)[lane];
        p.x += c4.x; p.y += c4.y; p.z += c4.z; p.w += c4.w;
    }
    float s = p.x + p.y + p.z + p.w;
    float sq = p.x*p.x + p.y*p.y + p.z*p.z + p.w*p.w;
    #pragma unroll
    for (int off = 16; off >= 1; off >>= 1) {
        s  += __shfl_xor_sync(0xffffffffu, s, off);
        sq += __shfl_xor_sync(0xffffffffu, sq, off);
    }
    float mu = s * (1.0f/HID);
    float var = sq * (1.0f/HID) - mu*mu;
    float rstd = rsqrtf(var + 1e-5f);
    float4 gg = ((const float4*)g)[lane];
    float4 bb = ((const float4*)b)[lane];
    float4 o;
    o.x = (p.x - mu)*rstd*gg.x + bb.x;
    o.y = (p.y - mu)*rstd*gg.y + bb.y;
    o.z = (p.z - mu)*rstd*gg.z + bb.z;
    o.w = (p.w - mu)*rstd*gg.w + bb.w;
    ((float4*)(out + (size_t)r*HID))[lane] = o;
}

// ---------------- launch ----------------
extern "C" void kernel_launch(void* const* d_in, const int* in_sizes, int n_in,
                              void* d_out, int out_size)
{
    const float* x_ball    = (const float*)d_in[0];
    const float* x_player  = (const float*)d_in[1];
    const float* x_context = (const float*)d_in[2];
    const int*   em   = (const int*)d_in[3];
    const int*   ep   = (const int*)d_in[4];
    const int*   ei   = (const int*)d_in[5];
    const float* ea_p = (const float*)d_in[6];
    const float* gWl  = (const float*)d_in[7];
    const float* gWr  = (const float*)d_in[8];
    const float* gatt = (const float*)d_in[9];
    const float* gb   = (const float*)d_in[10];
    const float* tWq  = (const float*)d_in[11];
    const float* tbq  = (const float*)d_in[12];
    const float* tWk  = (const float*)d_in[13];
    const float* tbk  = (const float*)d_in[14];
    const float* tWv  = (const float*)d_in[15];
    const float* tbv  = (const float*)d_in[16];
    const float* tWe  = (const float*)d_in[17];
    const float* tWs  = (const float*)d_in[18];
    const float* tbs  = (const float*)d_in[19];
    const float* sWl  = (const float*)d_in[20];
    const float* sbl  = (const float*)d_in[21];
    const float* sWr  = (const float*)d_in[22];
    const float* lbg  = (const float*)d_in[23];
    const float* lbb  = (const float*)d_in[24];
    const float* lcg  = (const float*)d_in[25];
    const float* lcb  = (const float*)d_in[26];
    float* out = (float*)d_out;

    float* base = nullptr;
    cudaGetSymbolAddress((void**)&base, g_buf);
    float* s_xl   = base + OFF_XL;
    float* s_xr   = base + OFF_XR;
    float* s_q    = base + OFF_Q;
    float* s_k    = base + OFF_K;
    float* s_v    = base + OFF_V;
    float* s_acc  = base + OFF_ACC;
    float* s_mean = base + OFF_MEAN;
    float* s_sage = base + OFF_SAGE;

    const int T = 256;

    cudaFuncSetAttribute(big5_mma, cudaFuncAttributeMaxDynamicSharedMemorySize, SMEM_BIG5);
    cudaFuncSetAttribute(sage_mma, cudaFuncAttributeMaxDynamicSharedMemorySize, SMEM_SAGE);

    // init sum/count buffers + weight prep (order: prep before big5)
    init_kernel<<<(NC*HID + T-1)/T, T>>>();
    prepW_kernel<<<(8*16384 + T-1)/T, T>>>(tWq, tWk, tWv, tWs, gWr, gWl, sWr, sWl);

    // fused HMMA GEMM: x_ball x {q,k,v,skip->acc,xr} + x_player x gWl -> xl
    big5_mma<<<NTILE + PTILE, 256, SMEM_BIG5>>>(x_ball, x_player,
                                                s_q, s_k, s_v, s_acc, s_xr, s_xl,
                                                tbq, tbk, tbv, tbs);

    // merged pass 1: logits+exp+sum (GAT, TR) and SAGE scatter
    pass1_kernel<<<PASS1_GRID, T>>>(em, gatt, ep, ea_p, tWe, ei, x_ball);

    // merged pass 2: weighted scatters (GAT, TR) and SAGE mean
    pass2_kernel<<<PASS2_GRID, T>>>(em, ep, ea_p, tWe);

    // sage = x_ctx@sWr + mean@sWl + sbl  (single HMMA kernel)
    sage_mma<<<CTILE, 256, SMEM_SAGE>>>(x_context, s_mean, s_sage, sbl);

    // outputs
    ln_kernel<<<(NB + 7)/8, T>>>(s_acc, x_ball, gb, lbg, lbb, out, NB);
    ln_kernel<<<(NC + 7)/8, T>>>(s_sage, x_context, nullptr, lcg, lcb, out + (size_t)NB*HID, NC);
    cudaMemcpyAsync(out + (size_t)(NB+NC)*HID, x_player, (size_t)NP*HID*sizeof(float),
                    cudaMemcpyDeviceToDevice);
}

// round 10
// speedup vs baseline: 5.1745x; 1.0955x over previous
#include <cuda_runtime.h>
#include <cuda_bf16.h>
#include <cstdint>

#define HID 128
#define NH 4
#define NB 60000
#define NP 2000
#define NC 4000
#define EM_N 150000
#define EP_N 300000
#define EI_N 150000
#define NTILE 469          // ceil(NB/128)
#define PTILE 16           // ceil(NP/128)
#define CTILE 32           // ceil(NC/128)

// block counts for edge passes (4 edges/warp, 8 warps/block => 32 edges/block)
#define BG1 ((EM_N/4 + 7)/8)
#define BT1 ((EP_N/4 + 7)/8)
#define BS1 ((EI_N/4 + 7)/8)
#define PASS_GRID (BG1 + BT1)

// setup kernel partition: zero blocks + weight-prep blocks
#define ZB ((NC*HID + 255)/256)          // 2000 blocks covers all zeroed ranges
#define PB ((8*16384 + 255)/256)         // 512 blocks
#define SETUP_GRID (ZB + PB)

// ---- scratch layout (floats) ----
#define SZ_NBH (NB*HID)
#define OFF_XL     0
#define OFF_XR     (OFF_XL + NP*HID)
#define OFF_Q      (OFF_XR + SZ_NBH)
#define OFF_K      (OFF_Q + SZ_NBH)
#define OFF_V      (OFF_K + SZ_NBH)
#define OFF_ACC    (OFF_V + SZ_NBH)
#define OFF_CTXSUM (OFF_ACC + SZ_NBH)
#define OFF_SAGE   (OFF_CTXSUM + NC*HID)
#define OFF_CNT    (OFF_SAGE + NC*HID)
#define OFF_GLOGIT (OFF_CNT + NC)
#define OFF_TLOGIT (OFF_GLOGIT + EM_N*NH)
#define OFF_GSUM   (OFF_TLOGIT + EP_N*NH)
#define OFF_TSUM   (OFF_GSUM + NB*NH)
#define TOTAL_SCRATCH (OFF_TSUM + NB*NH)

__device__ __align__(256) float g_buf[TOTAL_SCRATCH];

// pre-converted weights: 8 matrices x {hi,lo} in ldmatrix-ready layout (k*STR + n)
#define STR 136
#define WP_ELEMS (128*STR)          // 17408 bf16 = 34816 B
__device__ __align__(1024) __nv_bfloat16 g_Wprep[8*2*WP_ELEMS];

// ---------------- PTX helpers ----------------
__device__ __forceinline__ uint32_t smem_u32(const void* p) {
    uint32_t a;
    asm("{ .reg .u64 t; cvta.to.shared.u64 t, %1; cvt.u32.u64 %0, t; }" : "=r"(a) : "l"(p));
    return a;
}
__device__ __forceinline__ void ldsm4(uint32_t& r0, uint32_t& r1, uint32_t& r2, uint32_t& r3,
                                      uint32_t addr) {
    asm volatile("ldmatrix.sync.aligned.m8n8.x4.shared.b16 {%0,%1,%2,%3}, [%4];"
                 : "=r"(r0), "=r"(r1), "=r"(r2), "=r"(r3) : "r"(addr));
}
__device__ __forceinline__ void ldsm4t(uint32_t& r0, uint32_t& r1, uint32_t& r2, uint32_t& r3,
                                       uint32_t addr) {
    asm volatile("ldmatrix.sync.aligned.m8n8.x4.trans.shared.b16 {%0,%1,%2,%3}, [%4];"
                 : "=r"(r0), "=r"(r1), "=r"(r2), "=r"(r3) : "r"(addr));
}
__device__ __forceinline__ void mma16816(float* C, const uint32_t* A, uint32_t B0, uint32_t B1) {
    asm volatile("mma.sync.aligned.m16n8k16.row.col.f32.bf16.bf16.f32 "
                 "{%0,%1,%2,%3}, {%4,%5,%6,%7}, {%8,%9}, {%0,%1,%2,%3};"
                 : "+f"(C[0]), "+f"(C[1]), "+f"(C[2]), "+f"(C[3])
                 : "r"(A[0]), "r"(A[1]), "r"(A[2]), "r"(A[3]), "r"(B0), "r"(B1));
}
#define CP_ASYNC16(sm, gm) \
    asm volatile("cp.async.ca.shared.global [%0], [%1], 16;" :: "r"(sm), "l"(gm))
#define CP_COMMIT() asm volatile("cp.async.commit_group;" ::: "memory")
#define CP_WAIT1() asm volatile("cp.async.wait_group 1;" ::: "memory")
#define CP_WAIT0() asm volatile("cp.async.wait_group 0;" ::: "memory")

// ---------------- setup: zero stat buffers + weight prep (partitioned grid) ----------------
__global__ void setup_kernel(const float* __restrict__ w0, const float* __restrict__ w1,
                             const float* __restrict__ w2, const float* __restrict__ w3,
                             const float* __restrict__ w4, const float* __restrict__ w5,
                             const float* __restrict__ w6, const float* __restrict__ w7)
{
    unsigned b = blockIdx.x;
    if (b < ZB) {
        int i = b * 256 + threadIdx.x;
        if (i < NB*NH) {
            g_buf[OFF_GSUM + i] = 0.f;
            g_buf[OFF_TSUM + i] = 0.f;
        }
        if (i < NC*HID) g_buf[OFF_CTXSUM + i] = 0.f;
        if (i < NC) g_buf[OFF_CNT + i] = 0.f;
    } else {
        int idx = (b - ZB) * 256 + threadIdx.x;
        if (idx >= 8 * 16384) return;
        int m = idx >> 14, rem = idx & 16383;
        int k = rem >> 7, n = rem & 127;
        const float* W = (m == 0) ? w0 : (m == 1) ? w1 : (m == 2) ? w2 : (m == 3) ? w3
                       : (m == 4) ? w4 : (m == 5) ? w5 : (m == 6) ? w6 : w7;
        float v = W[(size_t)k * HID + n];
        __nv_bfloat16 hi = __float2bfloat16(v);
        __nv_bfloat16 lo = __float2bfloat16(v - __bfloat162float(hi));
        g_Wprep[(size_t)(m*2 + 0)*WP_ELEMS + k*STR + n] = hi;
        g_Wprep[(size_t)(m*2 + 1)*WP_ELEMS + k*STR + n] = lo;
    }
}

// ---------------- big HMMA GEMM: x_ball x {q,k,v,skip,xr}, x_player x {gWl} ----------------
#define SMA_H 0
#define SMA_L 34816
#define SMW0  69632
#define SMW1  139264
#define SMEM_BIG5 208896

__device__ __forceinline__ void stageW_async(uint32_t smW, int widx, int tid) {
    const char* gh = (const char*)g_Wprep + (size_t)(widx*2)*WP_ELEMS*2;
    const char* gl = gh + WP_ELEMS*2;
    for (int j = tid; j < 2176; j += 256) {
        CP_ASYNC16(smW + j*16, gh + j*16);
        CP_ASYNC16(smW + 34816 + j*16, gl + j*16);
    }
}

__global__ void __launch_bounds__(256)
big5_mma(const float* __restrict__ xball, const float* __restrict__ xplayer,
         float* __restrict__ o0, float* __restrict__ o1, float* __restrict__ o2,
         float* __restrict__ o3, float* __restrict__ o4, float* __restrict__ o5,
         const float* __restrict__ b0, const float* __restrict__ b1,
         const float* __restrict__ b2, const float* __restrict__ b3)
{
    extern __shared__ char smem[];
    const uint32_t sb = smem_u32(smem);
    const int tid = threadIdx.x, lane = tid & 31, warp = tid >> 5;
    const int wm = warp >> 1, wn = warp & 1;
    const bool player = (blockIdx.x >= NTILE);
    const int tile = player ? (blockIdx.x - NTILE) : blockIdx.x;
    const int rbase = tile * 128;
    const int nrows = player ? NP : NB;
    const float* Asrc = player ? xplayer : xball;
    const int nw = player ? 1 : 5;

    // stage A tile as hi/lo bf16
    for (int idx = tid; idx < 8192; idx += 256) {
        int row = idx >> 6, kp = idx & 63;
        int grow = rbase + row;
        float2 v = make_float2(0.f, 0.f);
        if (grow < nrows) v = ((const float2*)(Asrc + (size_t)grow * HID))[kp];
        __nv_bfloat162 h2 = __float22bfloat162_rn(v);
        float2 lo = make_float2(v.x - __bfloat162float(h2.x),
                                v.y - __bfloat162float(h2.y));
        __nv_bfloat162 l2 = __float22bfloat162_rn(lo);
        uint32_t off = (uint32_t)(row * STR + kp * 2) * 2;
        *(uint32_t*)(smem + SMA_H + off) = *(uint32_t*)&h2;
        *(uint32_t*)(smem + SMA_L + off) = *(uint32_t*)&l2;
    }

    // prefetch W[0]
    stageW_async(sb + SMW0, player ? 5 : 0, tid);
    CP_COMMIT();

    float*       outs[5]   = {o0, o1, o2, o3, o4};
    const float* biases[5] = {b0, b1, b2, b3, nullptr};

    const int gid = lane >> 2, tig = lane & 3;
    const int sub = lane >> 3, lr = lane & 7;
    const int f_r = ((sub & 1) << 3) + lr;
    const int f_c = (sub >> 1) << 3;

    for (int i = 0; i < nw; i++) {
        if (i + 1 < nw) {
            stageW_async(sb + (((i+1) & 1) ? SMW1 : SMW0), i + 1, tid);
            CP_COMMIT();
            CP_WAIT1();
        } else {
            CP_WAIT0();
        }
        __syncthreads();

        const uint32_t wbase = sb + ((i & 1) ? SMW1 : SMW0);

        float acc[2][8][4];
        #pragma unroll
        for (int mt = 0; mt < 2; mt++)
            #pragma unroll
            for (int j = 0; j < 8; j++)
                #pragma unroll
                for (int c = 0; c < 4; c++) acc[mt][j][c] = 0.f;

        #pragma unroll
        for (int ks = 0; ks < 8; ks++) {
            const int K0 = ks * 16;
            uint32_t ah[2][4], al[2][4];
            #pragma unroll
            for (int mt = 0; mt < 2; mt++) {
                uint32_t ad = sb + SMA_H +
                    (uint32_t)((wm*32 + mt*16 + f_r) * STR + K0 + f_c) * 2;
                ldsm4(ah[mt][0], ah[mt][1], ah[mt][2], ah[mt][3], ad);
                ldsm4(al[mt][0], al[mt][1], al[mt][2], al[mt][3], ad + (SMA_L - SMA_H));
            }
            uint32_t bh[4][4], bl[4][4];
            #pragma unroll
            for (int nt = 0; nt < 4; nt++) {
                uint32_t wd = wbase +
                    (uint32_t)((K0 + f_r) * STR + wn*64 + nt*16 + f_c) * 2;
                ldsm4t(bh[nt][0], bh[nt][1], bh[nt][2], bh[nt][3], wd);
                ldsm4t(bl[nt][0], bl[nt][1], bl[nt][2], bl[nt][3], wd + 34816);
            }
            #pragma unroll
            for (int mt = 0; mt < 2; mt++)
                #pragma unroll
                for (int nt = 0; nt < 4; nt++)
                    #pragma unroll
                    for (int h = 0; h < 2; h++) {
                        float* C = acc[mt][nt*2 + h];
                        mma16816(C, ah[mt], bh[nt][2*h], bh[nt][2*h+1]);
                        mma16816(C, ah[mt], bl[nt][2*h], bl[nt][2*h+1]);
                        mma16816(C, al[mt], bh[nt][2*h], bh[nt][2*h+1]);
                    }
        }

        const float* bias = player ? nullptr : biases[i];
        float* outp = player ? o5 : outs[i];
        #pragma unroll
        for (int mt = 0; mt < 2; mt++) {
            int r0g = rbase + wm*32 + mt*16 + gid;
            #pragma unroll
            for (int j = 0; j < 8; j++) {
                int cn = wn*64 + j*8 + tig*2;
                float bx = bias ? bias[cn]   : 0.f;
                float by = bias ? bias[cn+1] : 0.f;
                if (r0g < nrows)
                    *(float2*)(outp + (size_t)r0g*HID + cn) =
                        make_float2(acc[mt][j][0] + bx, acc[mt][j][1] + by);
                if (r0g + 8 < nrows)
                    *(float2*)(outp + (size_t)(r0g+8)*HID + cn) =
                        make_float2(acc[mt][j][2] + bx, acc[mt][j][3] + by);
            }
        }
        __syncthreads();
    }
}

// ---------------- sage HMMA: s_sage = x_ctx@sWr + (ctxsum/cnt)@sWl + sbl ----------------
#define SMEM_SAGE 139264

__global__ void __launch_bounds__(256)
sage_mma(const float* __restrict__ xctx, float* __restrict__ outp,
         const float* __restrict__ sbl)
{
    extern __shared__ char smem[];
    const uint32_t sb = smem_u32(smem);
    const int tid = threadIdx.x, lane = tid & 31, warp = tid >> 5;
    const int wm = warp >> 1, wn = warp & 1;
    const int rbase = blockIdx.x * 128;

    const int gid = lane >> 2, tig = lane & 3;
    const int sub = lane >> 3, lr = lane & 7;
    const int f_r = ((sub & 1) << 3) + lr;
    const int f_c = (sub >> 1) << 3;

    float acc[2][8][4];
    #pragma unroll
    for (int mt = 0; mt < 2; mt++)
        #pragma unroll
        for (int j = 0; j < 8; j++)
            #pragma unroll
            for (int c = 0; c < 4; c++) acc[mt][j][c] = 0.f;

    for (int it = 0; it < 2; it++) {
        const int widx = 6 + it;
        // stage A (it==1: mean = ctxsum / max(cnt,1), computed inline)
        for (int idx = tid; idx < 8192; idx += 256) {
            int row = idx >> 6, kp = idx & 63;
            int grow = rbase + row;
            float2 v = make_float2(0.f, 0.f);
            if (grow < NC) {
                if (it == 0) {
                    v = ((const float2*)(xctx + (size_t)grow * HID))[kp];
                } else {
                    v = ((const float2*)(g_buf + OFF_CTXSUM + (size_t)grow * HID))[kp];
                    float rc = 1.0f / fmaxf(g_buf[OFF_CNT + grow], 1.0f);
                    v.x *= rc; v.y *= rc;
                }
            }
            __nv_bfloat162 h2 = __float22bfloat162_rn(v);
            float2 lo = make_float2(v.x - __bfloat162float(h2.x),
                                    v.y - __bfloat162float(h2.y));
            __nv_bfloat162 l2 = __float22bfloat162_rn(lo);
            uint32_t off = (uint32_t)(row * STR + kp * 2) * 2;
            *(uint32_t*)(smem + SMA_H + off) = *(uint32_t*)&h2;
            *(uint32_t*)(smem + SMA_L + off) = *(uint32_t*)&l2;
        }
        // stage W (plain copy of prepped bf16)
        {
            const uint4* gh = (const uint4*)((const char*)g_Wprep + (size_t)(widx*2)*WP_ELEMS*2);
            const uint4* gl = (const uint4*)((const char*)g_Wprep + (size_t)(widx*2+1)*WP_ELEMS*2);
            uint4* dh = (uint4*)(smem + SMW0);
            uint4* dl = (uint4*)(smem + SMW0 + 34816);
            for (int j = tid; j < 2176; j += 256) { dh[j] = gh[j]; dl[j] = gl[j]; }
        }
        __syncthreads();

        #pragma unroll
        for (int ks = 0; ks < 8; ks++) {
            const int K0 = ks * 16;
            uint32_t ah[2][4], al[2][4];
            #pragma unroll
            for (int mt = 0; mt < 2; mt++) {
                uint32_t ad = sb + SMA_H +
                    (uint32_t)((wm*32 + mt*16 + f_r) * STR + K0 + f_c) * 2;
                ldsm4(ah[mt][0], ah[mt][1], ah[mt][2], ah[mt][3], ad);
                ldsm4(al[mt][0], al[mt][1], al[mt][2], al[mt][3], ad + (SMA_L - SMA_H));
            }
            uint32_t bh[4][4], bl[4][4];
            #pragma unroll
            for (int nt = 0; nt < 4; nt++) {
                uint32_t wd = sb + SMW0 +
                    (uint32_t)((K0 + f_r) * STR + wn*64 + nt*16 + f_c) * 2;
                ldsm4t(bh[nt][0], bh[nt][1], bh[nt][2], bh[nt][3], wd);
                ldsm4t(bl[nt][0], bl[nt][1], bl[nt][2], bl[nt][3], wd + 34816);
            }
            #pragma unroll
            for (int mt = 0; mt < 2; mt++)
                #pragma unroll
                for (int nt = 0; nt < 4; nt++)
                    #pragma unroll
                    for (int h = 0; h < 2; h++) {
                        float* C = acc[mt][nt*2 + h];
                        mma16816(C, ah[mt], bh[nt][2*h], bh[nt][2*h+1]);
                        mma16816(C, ah[mt], bl[nt][2*h], bl[nt][2*h+1]);
                        mma16816(C, al[mt], bh[nt][2*h], bh[nt][2*h+1]);
                    }
        }
        __syncthreads();
    }

    #pragma unroll
    for (int mt = 0; mt < 2; mt++) {
        int r0g = rbase + wm*32 + mt*16 + gid;
        #pragma unroll
        for (int j = 0; j < 8; j++) {
            int cn = wn*64 + j*8 + tig*2;
            float bx = sbl[cn], by = sbl[cn+1];
            if (r0g < NC)
                *(float2*)(outp + (size_t)r0g*HID + cn) =
                    make_float2(acc[mt][j][0] + bx, acc[mt][j][1] + by);
            if (r0g + 8 < NC)
                *(float2*)(outp + (size_t)(r0g+8)*HID + cn) =
                    make_float2(acc[mt][j][2] + bx, acc[mt][j][3] + by);
        }
    }
}

// ---------------- helpers ----------------
__device__ __forceinline__ void redAdd4(float* p, float a, float b, float c, float d) {
    asm volatile("red.global.add.v4.f32 [%0], {%1,%2,%3,%4};"
                 :: "l"(p), "f"(a), "f"(b), "f"(c), "f"(d) : "memory");
}

// ================= edge pass 1: logits + exp + segment sum (GAT, TR) =================
__global__ void __launch_bounds__(256)
pass1_kernel(const int* __restrict__ em, const float* __restrict__ att,
             const int* __restrict__ ep, const float* __restrict__ ea,
             const float* __restrict__ tWe)
{
    const int lane = threadIdx.x & 31;
    const int warp = threadIdx.x >> 5;
    const unsigned bx = blockIdx.x;

    if (bx < BG1) {
        int e0 = (bx * 8 + warp) << 2;
        if (e0 >= EM_N) return;
        int idx = 0;
        if (lane < 8) {
            int e = e0 + (lane & 3);
            if (e < EM_N) idx = em[(lane & 4) ? EM_N + e : e];
        }
        int ss[4], dd[4];
        #pragma unroll
        for (int j = 0; j < 4; j++) {
            ss[j] = __shfl_sync(0xffffffffu, idx, j);
            dd[j] = __shfl_sync(0xffffffffu, idx, 4 + j);
        }
        float4 at = ((const float4*)att)[lane];
        float4 xlv[4], xrv[4];
        #pragma unroll
        for (int j = 0; j < 4; j++) {
            if (e0 + j < EM_N) {
                xlv[j] = ((const float4*)(g_buf + OFF_XL + (size_t)ss[j]*HID))[lane];
                xrv[j] = ((const float4*)(g_buf + OFF_XR + (size_t)dd[j]*HID))[lane];
            }
        }
        #pragma unroll
        for (int j = 0; j < 4; j++) {
            if (e0 + j >= EM_N) break;
            float ex = xlv[j].x + xrv[j].x; ex = ex > 0.f ? ex : 0.2f*ex;
            float ey = xlv[j].y + xrv[j].y; ey = ey > 0.f ? ey : 0.2f*ey;
            float ez = xlv[j].z + xrv[j].z; ez = ez > 0.f ? ez : 0.2f*ez;
            float ew = xlv[j].w + xrv[j].w; ew = ew > 0.f ? ew : 0.2f*ew;
            float p = ex*at.x + ey*at.y + ez*at.z + ew*at.w;
            p += __shfl_xor_sync(0xffffffffu, p, 1);
            p += __shfl_xor_sync(0xffffffffu, p, 2);
            p += __shfl_xor_sync(0xffffffffu, p, 4);
            if ((lane & 7) == 0) {
                int h = lane >> 3;
                float e2 = __expf(p);
                g_buf[OFF_GLOGIT + (size_t)(e0 + j)*NH + h] = e2;
                atomicAdd(&g_buf[OFF_GSUM + (size_t)dd[j]*NH + h], e2);
            }
        }
    } else {
        int e0 = ((bx - BG1) * 8 + warp) << 2;
        if (e0 >= EP_N) return;
        int idx = 0;
        if (lane < 8) {
            int e = e0 + (lane & 3);
            if (e < EP_N) idx = ep[(lane & 4) ? EP_N + e : e];
        }
        float eav = 0.f;
        if (lane >= 8 && lane < 12) {
            int e = e0 + (lane & 3);
            if (e < EP_N) eav = ea[e];
        }
        int ss[4], dd[4]; float ev[4];
        #pragma unroll
        for (int j = 0; j < 4; j++) {
            ss[j] = __shfl_sync(0xffffffffu, idx, j);
            dd[j] = __shfl_sync(0xffffffffu, idx, 4 + j);
            ev[j] = __shfl_sync(0xffffffffu, eav, 8 + j);
        }
        float4 we = ((const float4*)tWe)[lane];
        float4 kv[4], qv[4];
        #pragma unroll
        for (int j = 0; j < 4; j++) {
            if (e0 + j < EP_N) {
                kv[j] = ((const float4*)(g_buf + OFF_K + (size_t)ss[j]*HID))[lane];
                qv[j] = ((const float4*)(g_buf + OFF_Q + (size_t)dd[j]*HID))[lane];
            }
        }
        #pragma unroll
        for (int j = 0; j < 4; j++) {
            if (e0 + j >= EP_N) break;
            float e = ev[j];
            float p = qv[j].x*(kv[j].x + e*we.x) + qv[j].y*(kv[j].y + e*we.y)
                    + qv[j].z*(kv[j].z + e*we.z) + qv[j].w*(kv[j].w + e*we.w);
            p += __shfl_xor_sync(0xffffffffu, p, 1);
            p += __shfl_xor_sync(0xffffffffu, p, 2);
            p += __shfl_xor_sync(0xffffffffu, p, 4);
            if ((lane & 7) == 0) {
                int h = lane >> 3;
                float e2 = __expf(p * 0.17677669529663689f);
                g_buf[OFF_TLOGIT + (size_t)(e0 + j)*NH + h] = e2;
                atomicAdd(&g_buf[OFF_TSUM + (size_t)dd[j]*NH + h], e2);
            }
        }
    }
}

// ================= edge pass 2: weighted scatters (GAT, TR) =================
__global__ void __launch_bounds__(256)
pass2_kernel(const int* __restrict__ em,
             const int* __restrict__ ep, const float* __restrict__ ea,
             const float* __restrict__ tWe)
{
    const int lane = threadIdx.x & 31;
    const int warp = threadIdx.x >> 5;
    const unsigned bx = blockIdx.x;

    if (bx < BG1) {
        int e0 = (bx * 8 + warp) << 2;
        if (e0 >= EM_N) return;
        int idx = 0;
        if (lane < 8) {
            int e = e0 + (lane & 3);
            if (e < EM_N) idx = em[(lane & 4) ? EM_N + e : e];
        }
        int ss[4], dd[4];
        #pragma unroll
        for (int j = 0; j < 4; j++) {
            ss[j] = __shfl_sync(0xffffffffu, idx, j);
            dd[j] = __shfl_sync(0xffffffffu, idx, 4 + j);
        }
        int h = lane >> 3;
        float lg[4], sm[4]; float4 xl[4];
        #pragma unroll
        for (int j = 0; j < 4; j++) {
            if (e0 + j < EM_N) {
                lg[j] = g_buf[OFF_GLOGIT + (size_t)(e0 + j)*NH + h];
                sm[j] = g_buf[OFF_GSUM + (size_t)dd[j]*NH + h];
                xl[j] = ((const float4*)(g_buf + OFF_XL + (size_t)ss[j]*HID))[lane];
            }
        }
        #pragma unroll
        for (int j = 0; j < 4; j++) {
            if (e0 + j >= EM_N) break;
            float alpha = lg[j] / (sm[j] + 1e-16f);
            redAdd4(g_buf + OFF_ACC + (size_t)dd[j]*HID + lane*4,
                    xl[j].x*alpha, xl[j].y*alpha, xl[j].z*alpha, xl[j].w*alpha);
        }
    } else {
        int e0 = ((bx - BG1) * 8 + warp) << 2;
        if (e0 >= EP_N) return;
        int idx = 0;
        if (lane < 8) {
            int e = e0 + (lane & 3);
            if (e < EP_N) idx = ep[(lane & 4) ? EP_N + e : e];
        }
        float eav = 0.f;
        if (lane >= 8 && lane < 12) {
            int e = e0 + (lane & 3);
            if (e < EP_N) eav = ea[e];
        }
        int ss[4], dd[4]; float ev[4];
        #pragma unroll
        for (int j = 0; j < 4; j++) {
            ss[j] = __shfl_sync(0xffffffffu, idx, j);
            dd[j] = __shfl_sync(0xffffffffu, idx, 4 + j);
            ev[j] = __shfl_sync(0xffffffffu, eav, 8 + j);
        }
        int h = lane >> 3;
        float4 we = ((const float4*)tWe)[lane];
        float lg[4], sm[4]; float4 vv[4];
        #pragma unroll
        for (int j = 0; j < 4; j++) {
            if (e0 + j < EP_N) {
                lg[j] = g_buf[OFF_TLOGIT + (size_t)(e0 + j)*NH + h];
                sm[j] = g_buf[OFF_TSUM + (size_t)dd[j]*NH + h];
                vv[j] = ((const float4*)(g_buf + OFF_V + (size_t)ss[j]*HID))[lane];
            }
        }
        #pragma unroll
        for (int j = 0; j < 4; j++) {
            if (e0 + j >= EP_N) break;
            float alpha = lg[j] / (sm[j] + 1e-16f);
            float e = ev[j];
            redAdd4(g_buf + OFF_ACC + (size_t)dd[j]*HID + lane*4,
                    (vv[j].x + e*we.x)*alpha, (vv[j].y + e*we.y)*alpha,
                    (vv[j].z + e*we.z)*alpha, (vv[j].w + e*we.w)*alpha);
        }
    }
}

// ================= SAGE scatter (side stream, overlaps big5) =================
__global__ void __launch_bounds__(256)
sage_scatter_kernel(const int* __restrict__ ei, const float* __restrict__ x_ball)
{
    int w = blockIdx.x * 8 + (threadIdx.x >> 5);
    int e0 = w << 2;
    if (e0 >= EI_N) return;
    int lane = threadIdx.x & 31;
    int idx = 0;
    if (lane < 8) {
        int e = e0 + (lane & 3);
        if (e < EI_N) idx = ei[(lane & 4) ? EI_N + e : e];
    }
    int ss[4], dd[4];
    #pragma unroll
    for (int j = 0; j < 4; j++) {
        ss[j] = __shfl_sync(0xffffffffu, idx, j);
        dd[j] = __shfl_sync(0xffffffffu, idx, 4 + j);
    }
    float4 xb[4];
    #pragma unroll
    for (int j = 0; j < 4; j++)
        if (e0 + j < EI_N)
            xb[j] = ((const float4*)(x_ball + (size_t)ss[j]*HID))[lane];
    #pragma unroll
    for (int j = 0; j < 4; j++) {
        if (e0 + j >= EI_N) break;
        redAdd4(g_buf + OFF_CTXSUM + (size_t)dd[j]*HID + lane*4,
                xb[j].x, xb[j].y, xb[j].z, xb[j].w);
        if (lane == 0) atomicAdd(&g_buf[OFF_CNT + dd[j]], 1.0f);
    }
}

// ---------------- LayerNorm: out = LN(A + B [+ bcast]) ----------------
__global__ void ln_kernel(const float* __restrict__ A, const float* __restrict__ B,
                          const float* __restrict__ bcast, const float* __restrict__ g,
                          const float* __restrict__ b, float* __restrict__ out, int n) {
    int r = (blockIdx.x << 3) + (threadIdx.x >> 5);
    if (r >= n) return;
    int lane = threadIdx.x & 31;
    float4 p = ((const float4*)(A + (size_t)r*HID))[lane];
    float4 q = ((const float4*)(B + (size_t)r*HID))[lane];
    p.x += q.x; p.y += q.y; p.z += q.z; p.w += q.w;
    if (bcast) {
        float4 c4 = ((const float4*)bcast)[lane];
        p.x += c4.x; p.y += c4.y; p.z += c4.z; p.w += c4.w;
    }
    float s = p.x + p.y + p.z + p.w;
    float sq = p.x*p.x + p.y*p.y + p.z*p.z + p.w*p.w;
    #pragma unroll
    for (int off = 16; off >= 1; off >>= 1) {
        s  += __shfl_xor_sync(0xffffffffu, s, off);
        sq += __shfl_xor_sync(0xffffffffu, sq, off);
    }
    float mu = s * (1.0f/HID);
    float var = sq * (1.0f/HID) - mu*mu;
    float rstd = rsqrtf(var + 1e-5f);
    float4 gg = ((const float4*)g)[lane];
    float4 bb = ((const float4*)b)[lane];
    float4 o;
    o.x = (p.x - mu)*rstd*gg.x + bb.x;
    o.y = (p.y - mu)*rstd*gg.y + bb.y;
    o.z = (p.z - mu)*rstd*gg.z + bb.z;
    o.w = (p.w - mu)*rstd*gg.w + bb.w;
    ((float4*)(out + (size_t)r*HID))[lane] = o;
}

// ---------------- launch ----------------
extern "C" void kernel_launch(void* const* d_in, const int* in_sizes, int n_in,
                              void* d_out, int out_size)
{
    const float* x_ball    = (const float*)d_in[0];
    const float* x_player  = (const float*)d_in[1];
    const float* x_context = (const float*)d_in[2];
    const int*   em   = (const int*)d_in[3];
    const int*   ep   = (const int*)d_in[4];
    const int*   ei   = (const int*)d_in[5];
    const float* ea_p = (const float*)d_in[6];
    const float* gWl  = (const float*)d_in[7];
    const float* gWr  = (const float*)d_in[8];
    const float* gatt = (const float*)d_in[9];
    const float* gb   = (const float*)d_in[10];
    const float* tWq  = (const float*)d_in[11];
    const float* tbq  = (const float*)d_in[12];
    const float* tWk  = (const float*)d_in[13];
    const float* tbk  = (const float*)d_in[14];
    const float* tWv  = (const float*)d_in[15];
    const float* tbv  = (const float*)d_in[16];
    const float* tWe  = (const float*)d_in[17];
    const float* tWs  = (const float*)d_in[18];
    const float* tbs  = (const float*)d_in[19];
    const float* sWl  = (const float*)d_in[20];
    const float* sbl  = (const float*)d_in[21];
    const float* sWr  = (const float*)d_in[22];
    const float* lbg  = (const float*)d_in[23];
    const float* lbb  = (const float*)d_in[24];
    const float* lcg  = (const float*)d_in[25];
    const float* lcb  = (const float*)d_in[26];
    float* out = (float*)d_out;

    float* base = nullptr;
    cudaGetSymbolAddress((void**)&base, g_buf);
    float* s_xl   = base + OFF_XL;
    float* s_xr   = base + OFF_XR;
    float* s_q    = base + OFF_Q;
    float* s_k    = base + OFF_K;
    float* s_v    = base + OFF_V;
    float* s_acc  = base + OFF_ACC;
    float* s_sage = base + OFF_SAGE;

    const int T = 256;

    // one-time host resources (streams/events, no device memory)
    static cudaStream_t s_side = nullptr;
    static cudaEvent_t e_setup = nullptr, e_side = nullptr;
    if (s_side == nullptr) {
        cudaStreamCreateWithFlags(&s_side, cudaStreamNonBlocking);
        cudaEventCreateWithFlags(&e_setup, cudaEventDisableTiming);
        cudaEventCreateWithFlags(&e_side, cudaEventDisableTiming);
        cudaFuncSetAttribute(big5_mma, cudaFuncAttributeMaxDynamicSharedMemorySize, SMEM_BIG5);
        cudaFuncSetAttribute(sage_mma, cudaFuncAttributeMaxDynamicSharedMemorySize, SMEM_SAGE);
    }

    // ---- main stream: setup -> big5 -> pass1 -> pass2 -> ln_ball ----
    setup_kernel<<<SETUP_GRID, T>>>(tWq, tWk, tWv, tWs, gWr, gWl, sWr, sWl);
    cudaEventRecord(e_setup, 0);

    big5_mma<<<NTILE + PTILE, 256, SMEM_BIG5>>>(x_ball, x_player,
                                                s_q, s_k, s_v, s_acc, s_xr, s_xl,
                                                tbq, tbk, tbv, tbs);

    // ---- side stream: player copy + full context pipeline (overlaps big5/pass1/pass2) ----
    cudaStreamWaitEvent(s_side, e_setup, 0);
    cudaMemcpyAsync(out + (size_t)(NB+NC)*HID, x_player, (size_t)NP*HID*sizeof(float),
                    cudaMemcpyDeviceToDevice, s_side);
    sage_scatter_kernel<<<BS1, T, 0, s_side>>>(ei, x_ball);
    sage_mma<<<CTILE, 256, SMEM_SAGE, s_side>>>(x_context, s_sage, sbl);
    ln_kernel<<<(NC + 7)/8, T, 0, s_side>>>(s_sage, x_context, nullptr, lcg, lcb,
                                            out + (size_t)NB*HID, NC);
    cudaEventRecord(e_side, s_side);

    // ---- main stream continues ----
    pass1_kernel<<<PASS_GRID, T>>>(em, gatt, ep, ea_p, tWe);
    pass2_kernel<<<PASS_GRID, T>>>(em, ep, ea_p, tWe);
    ln_kernel<<<(NB + 7)/8, T>>>(s_acc, x_ball, gb, lbg, lbb, out, NB);

    // join side stream before capture ends
    cudaStreamWaitEvent(0, e_side, 0);
}